// round 14
// baseline (speedup 1.0000x reference)
#include <cuda_runtime.h>
#include <cuda_bf16.h>
#include <cooperative_groups.h>
#include <math.h>

namespace cg = cooperative_groups;

typedef unsigned long long ull;
typedef unsigned int u32;

#define E_   1024
#define HID_ 1024
#define V_   32000
#define B_   32
#define S_   128
#define SB_  4096   // S_*B_
#define G4_  4096   // 4*HID_

// ---------------- device scratch (static, no allocation) ----------------
// Gate-interleaved preact columns: n = 4*j + g, g in {i,f,o,c}
__device__ float g_WhT[G4_ * HID_];     // [(4j+g)][k] fp32
__device__ float g_bcat[G4_];
__device__ float g_Xpre[SB_ * G4_];
__device__ float g_Hall[SB_ * HID_];
__device__ float g_Cst[B_ * HID_];
__device__ __nv_bfloat16 g_XeHi[SB_ * E_];
__device__ __nv_bfloat16 g_XeLo[SB_ * E_];
__device__ __nv_bfloat16 g_WxTHi[G4_ * E_];           // Wx^T [(4j+g)][k] hi/lo
__device__ __nv_bfloat16 g_WxTLo[G4_ * E_];
__device__ __nv_bfloat16 g_AHi[SB_ * HID_];
__device__ __nv_bfloat16 g_ALo[SB_ * HID_];
__device__ __nv_bfloat16 g_BHi[(size_t)V_ * HID_];
__device__ __nv_bfloat16 g_BLo[(size_t)V_ * HID_];
__device__ int g_is64;

// ---------------- helpers ----------------
__device__ __forceinline__ u32 smem_u32(const void* p) {
    u32 a;
    asm("{ .reg .u64 t; cvta.to.shared.u64 t, %1; cvt.u32.u64 %0, t; }" : "=r"(a) : "l"(p));
    return a;
}
__device__ __forceinline__ ull gptr(const void* p) {
    ull g; asm("cvta.to.global.u64 %0, %1;" : "=l"(g) : "l"(p)); return g;
}
#define CPASYNC16(dst, src) \
    asm volatile("cp.async.ca.shared.global [%0], [%1], 16;" :: "r"(dst), "l"(src))
#define CP_COMMIT()  asm volatile("cp.async.commit_group;")
#define CP_WAIT(n)   asm volatile("cp.async.wait_group %0;" :: "n"(n))

#define LDSM4(r, a) \
    asm volatile("ldmatrix.sync.aligned.m8n8.x4.shared.b16 {%0,%1,%2,%3}, [%4];" \
        : "=r"((r)[0]), "=r"((r)[1]), "=r"((r)[2]), "=r"((r)[3]) : "r"(a))

__device__ __forceinline__ void mma_bf16(float* d, const u32* a, const u32* b) {
    asm volatile("mma.sync.aligned.m16n8k16.row.col.f32.bf16.bf16.f32 "
        "{%0,%1,%2,%3}, {%4,%5,%6,%7}, {%8,%9}, {%0,%1,%2,%3};"
        : "+f"(d[0]), "+f"(d[1]), "+f"(d[2]), "+f"(d[3])
        : "r"(a[0]), "r"(a[1]), "r"(a[2]), "r"(a[3]), "r"(b[0]), "r"(b[1]));
}

__device__ __forceinline__ void split_bf16(float v, __nv_bfloat16& h, __nv_bfloat16& l) {
    h = __float2bfloat16(v);
    l = __float2bfloat16(v - __bfloat162float(h));
}

// ---------------- dtype detect ----------------
__global__ void detect_kernel(const int* __restrict__ X32)
{
    if (blockIdx.x == 0 && threadIdx.x == 0) {
        int o = 0;
#pragma unroll
        for (int i = 0; i < 32; ++i) o |= X32[2 * i + 1];
        g_is64 = (o == 0) ? 1 : 0;
    }
}

// ---------------- prep: gate-interleaved WhT fp32 + WxT bf16 hi/lo + bias + C ----------------
__global__ void prep_kernel(
    const float* __restrict__ Wxi, const float* __restrict__ Whi, const float* __restrict__ bi,
    const float* __restrict__ Wxf, const float* __restrict__ Whf, const float* __restrict__ bf,
    const float* __restrict__ Wxo, const float* __restrict__ Who, const float* __restrict__ bo,
    const float* __restrict__ Wxc, const float* __restrict__ Whc, const float* __restrict__ bc,
    const float* __restrict__ Cin)
{
    int idx = blockIdx.x * blockDim.x + threadIdx.x;
    if (idx < E_ * HID_) {
        int k = idx >> 10, j = idx & 1023;
        const float* wx[4] = { Wxi, Wxf, Wxo, Wxc };
        const float* wh[4] = { Whi, Whf, Who, Whc };
#pragma unroll
        for (int g = 0; g < 4; ++g) {
            size_t r = (size_t)(4 * j + g);
            float xv = wx[g][idx];
            __nv_bfloat16 h, l; split_bf16(xv, h, l);
            g_WxTHi[r * E_ + k] = h;
            g_WxTLo[r * E_ + k] = l;
            g_WhT[r * HID_ + k] = wh[g][idx];
        }
    }
    if (idx < G4_) {
        int j = idx >> 2, g = idx & 3;
        const float* bp = (g == 0) ? bi : (g == 1) ? bf : (g == 2) ? bo : bc;
        g_bcat[idx] = bp[j];
    }
    if (idx < B_ * HID_) g_Cst[idx] = Cin[idx];
}

// ---------------- gather + bf16 split ----------------
__global__ void gather_kernel(const void* __restrict__ Xraw, const float* __restrict__ emb)
{
    int id = blockIdx.x * blockDim.x + threadIdx.x;
    int r  = id >> 8;
    int k4 = (id & 255) << 2;
    int s = r >> 5, b = r & 31;
    int tok;
    if (g_is64) tok = (int)((const long long*)Xraw)[b * S_ + s];
    else        tok = ((const int*)Xraw)[b * S_ + s];
    float4 v = *(const float4*)&emb[(size_t)tok * E_ + k4];
    __nv_bfloat16 h0, l0, h1, l1, h2, l2, h3, l3;
    split_bf16(v.x, h0, l0); split_bf16(v.y, h1, l1);
    split_bf16(v.z, h2, l2); split_bf16(v.w, h3, l3);
    uint2 hp, lp;
    hp.x = (u32)__bfloat16_as_ushort(h0) | ((u32)__bfloat16_as_ushort(h1) << 16);
    hp.y = (u32)__bfloat16_as_ushort(h2) | ((u32)__bfloat16_as_ushort(h3) << 16);
    lp.x = (u32)__bfloat16_as_ushort(l0) | ((u32)__bfloat16_as_ushort(l1) << 16);
    lp.y = (u32)__bfloat16_as_ushort(l2) | ((u32)__bfloat16_as_ushort(l3) << 16);
    *(uint2*)&g_XeHi[r * E_ + k4] = hp;
    *(uint2*)&g_XeLo[r * E_ + k4] = lp;
}

// ---------------- Whq transpose + bf16 split ----------------
__global__ void wq_split(const float* __restrict__ Wq)
{
    __shared__ float t[32][33];
    int n0 = blockIdx.x * 32, k0 = blockIdx.y * 32;
    int tx = threadIdx.x, ty = threadIdx.y;   // 32 x 8
#pragma unroll
    for (int i = 0; i < 4; ++i) {
        int k = k0 + ty + i * 8;
        t[ty + i * 8][tx] = Wq[(size_t)k * V_ + n0 + tx];
    }
    __syncthreads();
#pragma unroll
    for (int i = 0; i < 4; ++i) {
        int n = n0 + ty + i * 8;
        float v = t[tx][ty + i * 8];
        __nv_bfloat16 h, l; split_bf16(v, h, l);
        g_BHi[(size_t)n * HID_ + k0 + tx] = h;
        g_BLo[(size_t)n * HID_ + k0 + tx] = l;
    }
}

// ---------------- generic split-bf16 HMMA GEMM (R8-proven: 128x128, 256 thr) ----------------
#define GEMM_SMEM 81920
__global__ __launch_bounds__(256, 2)
void gemm_mma(const __nv_bfloat16* __restrict__ Ahi, const __nv_bfloat16* __restrict__ Alo,
              const __nv_bfloat16* __restrict__ Bhi, const __nv_bfloat16* __restrict__ Blo,
              const float* __restrict__ bias, float* __restrict__ C, int ldc)
{
    extern __shared__ __align__(128) char smraw[];
    const u32 sbase = smem_u32(smraw);
    const int tid = threadIdx.x;
    const int lane = tid & 31, wid = tid >> 5;
    const int wm = (wid & 3) * 32, wn = (wid >> 2) * 64;
    const size_t m0 = (size_t)blockIdx.x * 128, n0 = (size_t)blockIdx.y * 128;

    ull gsrc[4];
    gsrc[0] = gptr(Ahi + m0 * 1024);
    gsrc[1] = gptr(Alo + m0 * 1024);
    gsrc[2] = gptr(Bhi + n0 * 1024);
    gsrc[3] = gptr(Blo + n0 * 1024);

    const int lrow = tid >> 2;
    const int lc16 = (tid & 3) * 16;

    auto load_chunk = [&](int ch, int buf) {
        const u32 bb = sbase + buf * 40960;
        const ull srcoff = (ull)ch * 64;
#pragma unroll
        for (int mat = 0; mat < 4; ++mat) {
            const ull src = gsrc[mat] + srcoff;
            const u32 dst = bb + mat * 10240;
#pragma unroll
            for (int j = 0; j < 2; ++j) {
                int row = lrow + j * 64;
                CPASYNC16(dst + row * 80 + lc16, (const void*)(src + (ull)row * 2048 + lc16));
            }
        }
        CP_COMMIT();
    };

    float acc[2][8][4];
#pragma unroll
    for (int mf = 0; mf < 2; ++mf)
#pragma unroll
        for (int nf = 0; nf < 8; ++nf)
#pragma unroll
            for (int q = 0; q < 4; ++q) acc[mf][nf][q] = 0.0f;

    load_chunk(0, 0);

    for (int ch = 0; ch < 32; ++ch) {
        if (ch < 31) { load_chunk(ch + 1, (ch + 1) & 1); CP_WAIT(1); }
        else         { CP_WAIT(0); }
        __syncthreads();
        const u32 bb = sbase + (ch & 1) * 40960;
#pragma unroll
        for (int ks = 0; ks < 2; ++ks) {
            u32 ah[8], al[8];
            const u32 arow = wm + (lane & 15);
            const u32 acol = ks * 32 + ((lane >> 4) << 4);
            const u32 a0 = bb + arow * 80 + acol;
            const u32 a1 = bb + (arow + 16) * 80 + acol;
            LDSM4(&ah[0], a0); LDSM4(&ah[4], a1);
            LDSM4(&al[0], a0 + 10240); LDSM4(&al[4], a1 + 10240);
#pragma unroll
            for (int p = 0; p < 4; ++p) {
                u32 bh[4], bl[4];
                const u32 brow = wn + p * 16 + (lane & 7) + ((lane & 16) ? 8 : 0);
                const u32 bcol = ks * 32 + ((lane & 8) ? 16 : 0);
                const u32 ba = bb + 20480 + brow * 80 + bcol;
                LDSM4(bh, ba); LDSM4(bl, ba + 10240);
#pragma unroll
                for (int mf = 0; mf < 2; ++mf)
#pragma unroll
                    for (int sub = 0; sub < 2; ++sub) {
                        float* d = acc[mf][p * 2 + sub];
                        mma_bf16(d, &ah[mf * 4], &bh[sub * 2]);   // hi*hi
                        mma_bf16(d, &ah[mf * 4], &bl[sub * 2]);   // hi*lo
                        mma_bf16(d, &al[mf * 4], &bh[sub * 2]);   // lo*hi
                    }
            }
        }
        __syncthreads();
    }

    const int r0 = lane >> 2, cp2 = (lane & 3) * 2;
#pragma unroll
    for (int mf = 0; mf < 2; ++mf) {
        const size_t row = m0 + wm + mf * 16 + r0;
#pragma unroll
        for (int nf = 0; nf < 8; ++nf) {
            const size_t col = n0 + wn + nf * 8 + cp2;
            const float b0 = bias[col], b1 = bias[col + 1];
            float2 v0 = { acc[mf][nf][0] + b0, acc[mf][nf][1] + b1 };
            float2 v1 = { acc[mf][nf][2] + b0, acc[mf][nf][3] + b1 };
            *(float2*)&C[row * (size_t)ldc + col] = v0;
            *(float2*)&C[(row + 8) * (size_t)ldc + col] = v1;
        }
    }
}

// ================= recurrence: CTA-owned columns, gate-interleaved =================
// CTA blk owns interleaved cols [blk*32, blk*32+32) = hidden units j0..j0+7, all 4 gates.
// Thread: jj = tid&7 (unit), bg = tid>>3 (batch pair). acc[2][4] = 2 batches x 4 gates.
// W slice (32 cols x 1024 k, stride 1028) resident in smem; h chunks (64 k) double-buffered.
#define WS_STRIDE 1028
#define H_OFF     (32 * WS_STRIDE)                       // floats
#define LSTM_SMEM ((32 * WS_STRIDE + 2 * 32 * 68) * 4)   // 148,992 B

__device__ __forceinline__ void lstm_load_W(float* wsm, int c0, int tid)
{
#pragma unroll
    for (int i = 0; i < 64; ++i) {
        int fidx = i * 128 + tid;                 // 8192 float4
        int col = fidx >> 8, seg = (fidx & 255) << 2;
        *(float4*)&wsm[col * WS_STRIDE + seg] =
            *(const float4*)&g_WhT[(size_t)(c0 + col) * HID_ + seg];
    }
}

__device__ __forceinline__ void lstm_step_body(float* wsm, float* hsm,
                                               const float* hprev, int s,
                                               int blk, int tid)
{
    const int jj = tid & 7, bg = tid >> 3;
    const int j0 = blk * 8;

    float4 hreg[4];
    auto ldg_h = [&](int k0) {
#pragma unroll
        for (int i = 0; i < 4; ++i) {
            int idx = i * 128 + tid; int row = idx >> 4, seg = (idx & 15) << 2;
            hreg[i] = *(const float4*)&hprev[row * HID_ + k0 + seg];
        }
    };
    auto sts_h = [&](int buf) {
        float* hb = hsm + buf * (32 * 68);
#pragma unroll
        for (int i = 0; i < 4; ++i) {
            int idx = i * 128 + tid; int row = idx >> 4, seg = (idx & 15) << 2;
            *(float4*)&hb[row * 68 + seg] = hreg[i];
        }
    };

    ldg_h(0);
    sts_h(0);
    __syncthreads();

    float acc[2][4];
#pragma unroll
    for (int bb = 0; bb < 2; ++bb)
#pragma unroll
        for (int g = 0; g < 4; ++g) acc[bb][g] = 0.0f;

    const float* w0 = wsm + (jj * 4 + 0) * WS_STRIDE;
    const float* w1 = wsm + (jj * 4 + 1) * WS_STRIDE;
    const float* w2 = wsm + (jj * 4 + 2) * WS_STRIDE;
    const float* w3 = wsm + (jj * 4 + 3) * WS_STRIDE;

    for (int ch = 0; ch < 16; ++ch) {
        const int cur = ch & 1;
        if (ch < 15) ldg_h((ch + 1) * 64);
        const float* hb = hsm + cur * (32 * 68);
        const int kg = ch * 64;
#pragma unroll
        for (int kk = 0; kk < 64; kk += 4) {
            float4 h0 = *(const float4*)&hb[(bg * 2 + 0) * 68 + kk];
            float4 h1 = *(const float4*)&hb[(bg * 2 + 1) * 68 + kk];
            float4 v0 = *(const float4*)&w0[kg + kk];
            float4 v1 = *(const float4*)&w1[kg + kk];
            float4 v2 = *(const float4*)&w2[kg + kk];
            float4 v3 = *(const float4*)&w3[kg + kk];
            acc[0][0] = fmaf(h0.x, v0.x, acc[0][0]); acc[0][0] = fmaf(h0.y, v0.y, acc[0][0]);
            acc[0][0] = fmaf(h0.z, v0.z, acc[0][0]); acc[0][0] = fmaf(h0.w, v0.w, acc[0][0]);
            acc[0][1] = fmaf(h0.x, v1.x, acc[0][1]); acc[0][1] = fmaf(h0.y, v1.y, acc[0][1]);
            acc[0][1] = fmaf(h0.z, v1.z, acc[0][1]); acc[0][1] = fmaf(h0.w, v1.w, acc[0][1]);
            acc[0][2] = fmaf(h0.x, v2.x, acc[0][2]); acc[0][2] = fmaf(h0.y, v2.y, acc[0][2]);
            acc[0][2] = fmaf(h0.z, v2.z, acc[0][2]); acc[0][2] = fmaf(h0.w, v2.w, acc[0][2]);
            acc[0][3] = fmaf(h0.x, v3.x, acc[0][3]); acc[0][3] = fmaf(h0.y, v3.y, acc[0][3]);
            acc[0][3] = fmaf(h0.z, v3.z, acc[0][3]); acc[0][3] = fmaf(h0.w, v3.w, acc[0][3]);
            acc[1][0] = fmaf(h1.x, v0.x, acc[1][0]); acc[1][0] = fmaf(h1.y, v0.y, acc[1][0]);
            acc[1][0] = fmaf(h1.z, v0.z, acc[1][0]); acc[1][0] = fmaf(h1.w, v0.w, acc[1][0]);
            acc[1][1] = fmaf(h1.x, v1.x, acc[1][1]); acc[1][1] = fmaf(h1.y, v1.y, acc[1][1]);
            acc[1][1] = fmaf(h1.z, v1.z, acc[1][1]); acc[1][1] = fmaf(h1.w, v1.w, acc[1][1]);
            acc[1][2] = fmaf(h1.x, v2.x, acc[1][2]); acc[1][2] = fmaf(h1.y, v2.y, acc[1][2]);
            acc[1][2] = fmaf(h1.z, v2.z, acc[1][2]); acc[1][2] = fmaf(h1.w, v2.w, acc[1][2]);
            acc[1][3] = fmaf(h1.x, v3.x, acc[1][3]); acc[1][3] = fmaf(h1.y, v3.y, acc[1][3]);
            acc[1][3] = fmaf(h1.z, v3.z, acc[1][3]); acc[1][3] = fmaf(h1.w, v3.w, acc[1][3]);
        }
        __syncthreads();
        if (ch < 15) {
            sts_h(cur ^ 1);
            __syncthreads();
        }
    }

    // local epilogue: 2 elements per thread (all gates local)
    const int j = j0 + jj;
#pragma unroll
    for (int bb = 0; bb < 2; ++bb) {
        const int b = bg * 2 + bb;
        float4 xp = *(const float4*)&g_Xpre[(size_t)(s * B_ + b) * G4_ + 4 * j];
        float p0 = acc[bb][0] + xp.x;
        float p1 = acc[bb][1] + xp.y;
        float p2 = acc[bb][2] + xp.z;
        float p3 = acc[bb][3] + xp.w;
        float I = 1.0f / (1.0f + expf(-p0));
        float F = 1.0f / (1.0f + expf(-p1));
        float O = 1.0f / (1.0f + expf(-p2));
        float Ct = tanhf(p3);
        const int cidx = b * HID_ + j;
        float c = F * g_Cst[cidx] + I * Ct;
        g_Cst[cidx] = c;
        float h = O * tanhf(c);
        const size_t hidx = (size_t)s * B_ * HID_ + cidx;
        g_Hall[hidx] = h;
        __nv_bfloat16 hh, hl; split_bf16(h, hh, hl);
        g_AHi[hidx] = hh;
        g_ALo[hidx] = hl;
    }
}

// ---------------- persistent cooperative recurrence (ONE sync per step) ----------------
__global__ __launch_bounds__(128, 1)
void lstm_persist(const float* __restrict__ Hin)
{
    extern __shared__ __align__(128) float sm[];
    float* wsm = sm;
    float* hsm = sm + H_OFF;
    cg::grid_group grid = cg::this_grid();
    const int tid = threadIdx.x;
    const int blk = blockIdx.x;

    lstm_load_W(wsm, blk * 32, tid);
    __syncthreads();

    for (int s = 0; s < S_; ++s) {
        const float* hprev = (s == 0) ? Hin : (g_Hall + (size_t)(s - 1) * B_ * HID_);
        lstm_step_body(wsm, hsm, hprev, s, blk, tid);
        grid.sync();
    }
}

// ---------------- fallback per-step kernel ----------------
__global__ __launch_bounds__(128)
void lstm_step_k(const float* __restrict__ Hin, int s)
{
    extern __shared__ __align__(128) float sm[];
    float* wsm = sm;
    float* hsm = sm + H_OFF;
    lstm_load_W(wsm, blockIdx.x * 32, threadIdx.x);
    __syncthreads();
    const float* hprev = (s == 0) ? Hin : (g_Hall + (size_t)(s - 1) * B_ * HID_);
    lstm_step_body(wsm, hsm, hprev, s, blockIdx.x, threadIdx.x);
}

// ---------------- tail: Hf, Cf ----------------
__global__ void tail_kernel(float* __restrict__ out, int out_size)
{
    const long YOFF = (long)SB_ * V_;
    int idx = blockIdx.x * blockDim.x + threadIdx.x;
    if ((long)out_size >= YOFF + 2L * B_ * HID_) {
        out[YOFF + idx] = g_Hall[(S_ - 1) * B_ * HID_ + idx];
        out[YOFF + B_ * HID_ + idx] = g_Cst[idx];
    }
}

// ---------------- launch ----------------
extern "C" void kernel_launch(void* const* d_in, const int* in_sizes, int n_in,
                              void* d_out, int out_size)
{
    const void*  X   = d_in[0];
    const float* H0  = (const float*)d_in[1];
    const float* C0  = (const float*)d_in[2];
    const float* emb = (const float*)d_in[3];
    const float* Wxi = (const float*)d_in[4];
    const float* Whi = (const float*)d_in[5];
    const float* bi  = (const float*)d_in[6];
    const float* Wxf = (const float*)d_in[7];
    const float* Whf = (const float*)d_in[8];
    const float* bf  = (const float*)d_in[9];
    const float* Wxo = (const float*)d_in[10];
    const float* Who = (const float*)d_in[11];
    const float* bo  = (const float*)d_in[12];
    const float* Wxc = (const float*)d_in[13];
    const float* Whc = (const float*)d_in[14];
    const float* bc  = (const float*)d_in[15];
    const float* Whq = (const float*)d_in[16];
    const float* bq  = (const float*)d_in[17];
    float* out = (float*)d_out;

    void *pXeHi, *pXeLo, *pWxTHi, *pWxTLo, *pAHi, *pALo, *pBHi, *pBLo, *pb, *pXpre;
    cudaGetSymbolAddress(&pXeHi,  g_XeHi);
    cudaGetSymbolAddress(&pXeLo,  g_XeLo);
    cudaGetSymbolAddress(&pWxTHi, g_WxTHi);
    cudaGetSymbolAddress(&pWxTLo, g_WxTLo);
    cudaGetSymbolAddress(&pAHi,   g_AHi);
    cudaGetSymbolAddress(&pALo,   g_ALo);
    cudaGetSymbolAddress(&pBHi,   g_BHi);
    cudaGetSymbolAddress(&pBLo,   g_BLo);
    cudaGetSymbolAddress(&pb,     g_bcat);
    cudaGetSymbolAddress(&pXpre,  g_Xpre);

    cudaFuncSetAttribute(gemm_mma,     cudaFuncAttributeMaxDynamicSharedMemorySize, GEMM_SMEM);
    cudaFuncSetAttribute(lstm_persist, cudaFuncAttributeMaxDynamicSharedMemorySize, LSTM_SMEM);
    cudaFuncSetAttribute(lstm_step_k,  cudaFuncAttributeMaxDynamicSharedMemorySize, LSTM_SMEM);

    detect_kernel<<<1, 32>>>((const int*)X);
    prep_kernel<<<4096, 256>>>(Wxi, Whi, bi, Wxf, Whf, bf,
                               Wxo, Who, bo, Wxc, Whc, bc, C0);
    gather_kernel<<<4096, 256>>>(X, emb);
    wq_split<<<dim3(V_ / 32, HID_ / 32), dim3(32, 8)>>>(Whq);

    // Xpre = Xe @ Wx^T + bcat   (M=4096, N=4096 gate-interleaved, K=1024)
    gemm_mma<<<dim3(SB_ / 128, G4_ / 128), 256, GEMM_SMEM>>>(
        (const __nv_bfloat16*)pXeHi, (const __nv_bfloat16*)pXeLo,
        (const __nv_bfloat16*)pWxTHi, (const __nv_bfloat16*)pWxTLo,
        (const float*)pb, (float*)pXpre, G4_);

    // recurrence: cooperative persistent kernel (1 sync/step); fallback = per-step launches
    {
        const float* h0 = H0;
        void* args[1] = { (void*)&h0 };
        cudaError_t ce = cudaLaunchCooperativeKernel(
            (const void*)lstm_persist, dim3(128), dim3(128), args, (size_t)LSTM_SMEM, (cudaStream_t)0);
        if (ce != cudaSuccess) {
            cudaGetLastError();   // clear sticky error
            for (int s = 0; s < S_; ++s)
                lstm_step_k<<<128, 128, LSTM_SMEM>>>(H0, s);
        }
    }

    // Y = Hall @ Whq + bq  (M=4096, N=32000, K=1024)
    gemm_mma<<<dim3(SB_ / 128, V_ / 128), 256, GEMM_SMEM>>>(
        (const __nv_bfloat16*)pAHi, (const __nv_bfloat16*)pALo,
        (const __nv_bfloat16*)pBHi, (const __nv_bfloat16*)pBLo,
        bq, out, V_);

    tail_kernel<<<128, 256>>>(out, out_size);
}

// round 15
// speedup vs baseline: 1.5644x; 1.5644x over previous
#include <cuda_runtime.h>
#include <cuda_bf16.h>
#include <cooperative_groups.h>
#include <math.h>

namespace cg = cooperative_groups;

typedef unsigned long long ull;
typedef unsigned int u32;

#define E_   1024
#define HID_ 1024
#define V_   32000
#define B_   32
#define S_   128
#define SB_  4096   // S_*B_
#define G4_  4096   // 4*HID_

// ---------------- device scratch (static, no allocation) ----------------
// Gate-interleaved preact columns: n = 4*j + g, g in {i,f,o,c}
__device__ float g_bcat[G4_];
__device__ float g_Xpre[SB_ * G4_];
__device__ float g_Hall[SB_ * HID_];
__device__ float g_Cst[B_ * HID_];
__device__ __nv_bfloat16 g_XeHi[SB_ * E_];            // embedded inputs hi/lo
__device__ __nv_bfloat16 g_XeLo[SB_ * E_];
__device__ __nv_bfloat16 g_WxTHi[G4_ * E_];           // Wx^T [4j+g][k] hi/lo
__device__ __nv_bfloat16 g_WxTLo[G4_ * E_];
__device__ __nv_bfloat16 g_WhHi[G4_ * HID_];          // Wh^T [4j+g][k] hi/lo
__device__ __nv_bfloat16 g_WhLo[G4_ * HID_];
__device__ __nv_bfloat16 g_AHi[SB_ * HID_];           // h_t hi/lo (written by step epilogue)
__device__ __nv_bfloat16 g_ALo[SB_ * HID_];
__device__ __nv_bfloat16 g_H0Hi[B_ * HID_];           // split H0
__device__ __nv_bfloat16 g_H0Lo[B_ * HID_];
__device__ __nv_bfloat16 g_BHi[(size_t)V_ * HID_];    // Whq^T [n][k] hi/lo
__device__ __nv_bfloat16 g_BLo[(size_t)V_ * HID_];
__device__ int g_is64;

// ---------------- helpers ----------------
__device__ __forceinline__ u32 smem_u32(const void* p) {
    u32 a;
    asm("{ .reg .u64 t; cvta.to.shared.u64 t, %1; cvt.u32.u64 %0, t; }" : "=r"(a) : "l"(p));
    return a;
}
__device__ __forceinline__ ull gptr(const void* p) {
    ull g; asm("cvta.to.global.u64 %0, %1;" : "=l"(g) : "l"(p)); return g;
}
#define CPASYNC16(dst, src) \
    asm volatile("cp.async.ca.shared.global [%0], [%1], 16;" :: "r"(dst), "l"(src))
#define CP_COMMIT()  asm volatile("cp.async.commit_group;")
#define CP_WAIT(n)   asm volatile("cp.async.wait_group %0;" :: "n"(n))

#define LDSM4(r, a) \
    asm volatile("ldmatrix.sync.aligned.m8n8.x4.shared.b16 {%0,%1,%2,%3}, [%4];" \
        : "=r"((r)[0]), "=r"((r)[1]), "=r"((r)[2]), "=r"((r)[3]) : "r"(a))

__device__ __forceinline__ void mma_bf16(float* d, const u32* a, const u32* b) {
    asm volatile("mma.sync.aligned.m16n8k16.row.col.f32.bf16.bf16.f32 "
        "{%0,%1,%2,%3}, {%4,%5,%6,%7}, {%8,%9}, {%0,%1,%2,%3};"
        : "+f"(d[0]), "+f"(d[1]), "+f"(d[2]), "+f"(d[3])
        : "r"(a[0]), "r"(a[1]), "r"(a[2]), "r"(a[3]), "r"(b[0]), "r"(b[1]));
}

__device__ __forceinline__ void split_bf16(float v, __nv_bfloat16& h, __nv_bfloat16& l) {
    h = __float2bfloat16(v);
    l = __float2bfloat16(v - __bfloat162float(h));
}

// ---------------- dtype detect ----------------
__global__ void detect_kernel(const int* __restrict__ X32)
{
    if (blockIdx.x == 0 && threadIdx.x == 0) {
        int o = 0;
#pragma unroll
        for (int i = 0; i < 32; ++i) o |= X32[2 * i + 1];
        g_is64 = (o == 0) ? 1 : 0;
    }
}

// ---------------- prep: Wx^T / Wh^T bf16 hi/lo gate-interleaved, bias, C, H0 split ----------------
__global__ void prep_kernel(
    const float* __restrict__ Wxi, const float* __restrict__ Whi, const float* __restrict__ bi,
    const float* __restrict__ Wxf, const float* __restrict__ Whf, const float* __restrict__ bf,
    const float* __restrict__ Wxo, const float* __restrict__ Who, const float* __restrict__ bo,
    const float* __restrict__ Wxc, const float* __restrict__ Whc, const float* __restrict__ bc,
    const float* __restrict__ Cin, const float* __restrict__ Hin)
{
    int idx = blockIdx.x * blockDim.x + threadIdx.x;
    if (idx < E_ * HID_) {
        int k = idx >> 10, j = idx & 1023;
        const float* wx[4] = { Wxi, Wxf, Wxo, Wxc };
        const float* wh[4] = { Whi, Whf, Who, Whc };
#pragma unroll
        for (int g = 0; g < 4; ++g) {
            size_t r = (size_t)(4 * j + g);          // gate-interleaved
            __nv_bfloat16 h, l;
            split_bf16(wx[g][idx], h, l);
            g_WxTHi[r * E_ + k] = h;
            g_WxTLo[r * E_ + k] = l;
            split_bf16(wh[g][idx], h, l);
            g_WhHi[r * HID_ + k] = h;
            g_WhLo[r * HID_ + k] = l;
        }
    }
    if (idx < G4_) {
        int j = idx >> 2, g = idx & 3;
        const float* bp = (g == 0) ? bi : (g == 1) ? bf : (g == 2) ? bo : bc;
        g_bcat[idx] = bp[j];
    }
    if (idx < B_ * HID_) {
        g_Cst[idx] = Cin[idx];
        __nv_bfloat16 h, l; split_bf16(Hin[idx], h, l);
        g_H0Hi[idx] = h;
        g_H0Lo[idx] = l;
    }
}

// ---------------- gather + bf16 split ----------------
__global__ void gather_kernel(const void* __restrict__ Xraw, const float* __restrict__ emb)
{
    int id = blockIdx.x * blockDim.x + threadIdx.x;    // SB_*E_/4
    int r  = id >> 8;
    int k4 = (id & 255) << 2;
    int s = r >> 5, b = r & 31;
    int tok;
    if (g_is64) tok = (int)((const long long*)Xraw)[b * S_ + s];
    else        tok = ((const int*)Xraw)[b * S_ + s];
    float4 v = *(const float4*)&emb[(size_t)tok * E_ + k4];
    __nv_bfloat16 h0, l0, h1, l1, h2, l2, h3, l3;
    split_bf16(v.x, h0, l0); split_bf16(v.y, h1, l1);
    split_bf16(v.z, h2, l2); split_bf16(v.w, h3, l3);
    uint2 hp, lp;
    hp.x = (u32)__bfloat16_as_ushort(h0) | ((u32)__bfloat16_as_ushort(h1) << 16);
    hp.y = (u32)__bfloat16_as_ushort(h2) | ((u32)__bfloat16_as_ushort(h3) << 16);
    lp.x = (u32)__bfloat16_as_ushort(l0) | ((u32)__bfloat16_as_ushort(l1) << 16);
    lp.y = (u32)__bfloat16_as_ushort(l2) | ((u32)__bfloat16_as_ushort(l3) << 16);
    *(uint2*)&g_XeHi[r * E_ + k4] = hp;
    *(uint2*)&g_XeLo[r * E_ + k4] = lp;
}

// ---------------- Whq transpose + bf16 split ----------------
__global__ void wq_split(const float* __restrict__ Wq)
{
    __shared__ float t[32][33];
    int n0 = blockIdx.x * 32, k0 = blockIdx.y * 32;
    int tx = threadIdx.x, ty = threadIdx.y;   // 32 x 8
#pragma unroll
    for (int i = 0; i < 4; ++i) {
        int k = k0 + ty + i * 8;
        t[ty + i * 8][tx] = Wq[(size_t)k * V_ + n0 + tx];
    }
    __syncthreads();
#pragma unroll
    for (int i = 0; i < 4; ++i) {
        int n = n0 + ty + i * 8;
        float v = t[tx][ty + i * 8];
        __nv_bfloat16 h, l; split_bf16(v, h, l);
        g_BHi[(size_t)n * HID_ + k0 + tx] = h;
        g_BLo[(size_t)n * HID_ + k0 + tx] = l;
    }
}

// ---------------- generic split-bf16 HMMA GEMM (R8-proven: 128x128, 256 thr) ----------------
#define GEMM_SMEM 81920
__global__ __launch_bounds__(256, 2)
void gemm_mma(const __nv_bfloat16* __restrict__ Ahi, const __nv_bfloat16* __restrict__ Alo,
              const __nv_bfloat16* __restrict__ Bhi, const __nv_bfloat16* __restrict__ Blo,
              const float* __restrict__ bias, float* __restrict__ C, int ldc)
{
    extern __shared__ __align__(128) char smraw[];
    const u32 sbase = smem_u32(smraw);
    const int tid = threadIdx.x;
    const int lane = tid & 31, wid = tid >> 5;
    const int wm = (wid & 3) * 32, wn = (wid >> 2) * 64;
    const size_t m0 = (size_t)blockIdx.x * 128, n0 = (size_t)blockIdx.y * 128;

    ull gsrc[4];
    gsrc[0] = gptr(Ahi + m0 * 1024);
    gsrc[1] = gptr(Alo + m0 * 1024);
    gsrc[2] = gptr(Bhi + n0 * 1024);
    gsrc[3] = gptr(Blo + n0 * 1024);

    const int lrow = tid >> 2;
    const int lc16 = (tid & 3) * 16;

    auto load_chunk = [&](int ch, int buf) {
        const u32 bb = sbase + buf * 40960;
        const ull srcoff = (ull)ch * 64;
#pragma unroll
        for (int mat = 0; mat < 4; ++mat) {
            const ull src = gsrc[mat] + srcoff;
            const u32 dst = bb + mat * 10240;
#pragma unroll
            for (int j = 0; j < 2; ++j) {
                int row = lrow + j * 64;
                CPASYNC16(dst + row * 80 + lc16, (const void*)(src + (ull)row * 2048 + lc16));
            }
        }
        CP_COMMIT();
    };

    float acc[2][8][4];
#pragma unroll
    for (int mf = 0; mf < 2; ++mf)
#pragma unroll
        for (int nf = 0; nf < 8; ++nf)
#pragma unroll
            for (int q = 0; q < 4; ++q) acc[mf][nf][q] = 0.0f;

    load_chunk(0, 0);

    for (int ch = 0; ch < 32; ++ch) {
        if (ch < 31) { load_chunk(ch + 1, (ch + 1) & 1); CP_WAIT(1); }
        else         { CP_WAIT(0); }
        __syncthreads();
        const u32 bb = sbase + (ch & 1) * 40960;
#pragma unroll
        for (int ks = 0; ks < 2; ++ks) {
            u32 ah[8], al[8];
            const u32 arow = wm + (lane & 15);
            const u32 acol = ks * 32 + ((lane >> 4) << 4);
            const u32 a0 = bb + arow * 80 + acol;
            const u32 a1 = bb + (arow + 16) * 80 + acol;
            LDSM4(&ah[0], a0); LDSM4(&ah[4], a1);
            LDSM4(&al[0], a0 + 10240); LDSM4(&al[4], a1 + 10240);
#pragma unroll
            for (int p = 0; p < 4; ++p) {
                u32 bh[4], bl[4];
                const u32 brow = wn + p * 16 + (lane & 7) + ((lane & 16) ? 8 : 0);
                const u32 bcol = ks * 32 + ((lane & 8) ? 16 : 0);
                const u32 ba = bb + 20480 + brow * 80 + bcol;
                LDSM4(bh, ba); LDSM4(bl, ba + 10240);
#pragma unroll
                for (int mf = 0; mf < 2; ++mf)
#pragma unroll
                    for (int sub = 0; sub < 2; ++sub) {
                        float* d = acc[mf][p * 2 + sub];
                        mma_bf16(d, &ah[mf * 4], &bh[sub * 2]);   // hi*hi
                        mma_bf16(d, &ah[mf * 4], &bl[sub * 2]);   // hi*lo
                        mma_bf16(d, &al[mf * 4], &bh[sub * 2]);   // lo*hi
                    }
            }
        }
        __syncthreads();
    }

    const int r0 = lane >> 2, cp2 = (lane & 3) * 2;
#pragma unroll
    for (int mf = 0; mf < 2; ++mf) {
        const size_t row = m0 + wm + mf * 16 + r0;
#pragma unroll
        for (int nf = 0; nf < 8; ++nf) {
            const size_t col = n0 + wn + nf * 8 + cp2;
            const float b0 = bias[col], b1 = bias[col + 1];
            float2 v0 = { acc[mf][nf][0] + b0, acc[mf][nf][1] + b1 };
            float2 v1 = { acc[mf][nf][2] + b0, acc[mf][nf][3] + b1 };
            *(float2*)&C[row * (size_t)ldc + col] = v0;
            *(float2*)&C[(row + 8) * (size_t)ldc + col] = v1;
        }
    }
}

// ================= HMMA LSTM step body (R11-validated, verbatim) =================
// 64 CTAs (N-tile 64 = 16 j), 128 thr / 4 warps (warp n-tile 16 = 4 j).
// M=32=batch, K=1024 in 32 chunks of 32 elems. 3 acc banks (one per split term).
// Epilogue: + Xpre, shfl_xor(1) gate exchange, cell update, h + hi/lo split.
__device__ __forceinline__ void lstm_mma_body(char* smbase, int s, int blk, int tid)
{
    const int lane = tid & 31, wid = tid >> 5;
    const int n0 = blk * 64;

    const __nv_bfloat16* hHi = (s == 0) ? g_H0Hi : (g_AHi + (size_t)(s - 1) * B_ * HID_);
    const __nv_bfloat16* hLo = (s == 0) ? g_H0Lo : (g_ALo + (size_t)(s - 1) * B_ * HID_);
    const ull srcA[2] = { gptr(hHi), gptr(hLo) };
    const ull srcB[2] = { gptr(g_WhHi + (size_t)n0 * HID_), gptr(g_WhLo + (size_t)n0 * HID_) };

    const int lrow = tid >> 2;            // 0..31
    const int lc16 = (tid & 3) * 16;

    auto load_chunk = [&](int ch, int buf) {
        const u32 bb = smem_u32(smbase + buf * 15360);
        const ull off = (ull)ch * 64;
#pragma unroll
        for (int t = 0; t < 2; ++t) {     // hi/lo
            CPASYNC16(bb + t * 2560 + lrow * 80 + lc16,
                      (const void*)(srcA[t] + off + (ull)lrow * 2048 + lc16));
#pragma unroll
            for (int j = 0; j < 2; ++j) {
                int row = lrow + j * 32;
                CPASYNC16(bb + 5120 + t * 5120 + row * 80 + lc16,
                          (const void*)(srcB[t] + off + (ull)row * 2048 + lc16));
            }
        }
        CP_COMMIT();
    };

    float a0[2][2][4], a1[2][2][4], a2[2][2][4];   // 3 term banks [mf][sub][q]
#pragma unroll
    for (int mf = 0; mf < 2; ++mf)
#pragma unroll
        for (int sub = 0; sub < 2; ++sub)
#pragma unroll
            for (int q = 0; q < 4; ++q) { a0[mf][sub][q] = 0.f; a1[mf][sub][q] = 0.f; a2[mf][sub][q] = 0.f; }

    load_chunk(0, 0);

    for (int ch = 0; ch < 32; ++ch) {
        if (ch < 31) { load_chunk(ch + 1, (ch + 1) & 1); CP_WAIT(1); }
        else         { CP_WAIT(0); }
        __syncthreads();
        const u32 bb = smem_u32(smbase + (ch & 1) * 15360);
#pragma unroll
        for (int ks = 0; ks < 2; ++ks) {
            u32 ah[8], al[8];
            const u32 arow = lane & 15;
            const u32 acol = ks * 32 + ((lane >> 4) << 4);
            const u32 aa = bb + arow * 80 + acol;
            const u32 ab = bb + (arow + 16) * 80 + acol;
            LDSM4(&ah[0], aa); LDSM4(&ah[4], ab);
            LDSM4(&al[0], aa + 2560); LDSM4(&al[4], ab + 2560);
            u32 bh[4], bl[4];
            const u32 brow = wid * 16 + (lane & 7) + ((lane & 16) ? 8 : 0);
            const u32 bcol = ks * 32 + ((lane & 8) ? 16 : 0);
            const u32 ba = bb + 5120 + brow * 80 + bcol;
            LDSM4(bh, ba); LDSM4(bl, ba + 5120);
#pragma unroll
            for (int mf = 0; mf < 2; ++mf)
#pragma unroll
                for (int sub = 0; sub < 2; ++sub) {
                    mma_bf16(a0[mf][sub], &ah[mf * 4], &bh[sub * 2]);   // hi*hi
                    mma_bf16(a1[mf][sub], &ah[mf * 4], &bl[sub * 2]);   // hi*lo
                    mma_bf16(a2[mf][sub], &al[mf * 4], &bh[sub * 2]);   // lo*hi
                }
        }
        __syncthreads();
    }

    // ---- epilogue ----
    const int r0 = lane >> 2;             // c-frag row within 16
    const int cp2 = (lane & 3) * 2;       // col pair within 8
    float* hall = g_Hall + (size_t)s * B_ * HID_;
    __nv_bfloat16* ahi = g_AHi + (size_t)s * B_ * HID_;
    __nv_bfloat16* alo = g_ALo + (size_t)s * B_ * HID_;

#pragma unroll
    for (int mf = 0; mf < 2; ++mf) {
#pragma unroll
        for (int sub = 0; sub < 2; ++sub) {
            const int n = n0 + wid * 16 + sub * 8 + cp2;      // global preact col (even lane: 4j)
            const int b0r = mf * 16 + r0;                      // batch rows
            const int b1r = b0r + 8;
            float2 xp0 = *(const float2*)&g_Xpre[(size_t)(s * B_ + b0r) * G4_ + n];
            float2 xp1 = *(const float2*)&g_Xpre[(size_t)(s * B_ + b1r) * G4_ + n];
            float p00 = a0[mf][sub][0] + a1[mf][sub][0] + a2[mf][sub][0] + xp0.x;
            float p01 = a0[mf][sub][1] + a1[mf][sub][1] + a2[mf][sub][1] + xp0.y;
            float p10 = a0[mf][sub][2] + a1[mf][sub][2] + a2[mf][sub][2] + xp1.x;
            float p11 = a0[mf][sub][3] + a1[mf][sub][3] + a2[mf][sub][3] + xp1.y;
            float o00 = __shfl_xor_sync(0xffffffffu, p00, 1);
            float o01 = __shfl_xor_sync(0xffffffffu, p01, 1);
            float o10 = __shfl_xor_sync(0xffffffffu, p10, 1);
            float o11 = __shfl_xor_sync(0xffffffffu, p11, 1);
            if (!(lane & 1)) {
                const int j = n >> 2;
                {
                    const int cidx = b0r * HID_ + j;
                    float I = 1.0f / (1.0f + expf(-p00));
                    float F = 1.0f / (1.0f + expf(-p01));
                    float O = 1.0f / (1.0f + expf(-o00));
                    float c = F * g_Cst[cidx] + I * tanhf(o01);
                    g_Cst[cidx] = c;
                    float h = O * tanhf(c);
                    hall[cidx] = h;
                    __nv_bfloat16 hh, hl; split_bf16(h, hh, hl);
                    ahi[cidx] = hh; alo[cidx] = hl;
                }
                {
                    const int cidx = b1r * HID_ + j;
                    float I = 1.0f / (1.0f + expf(-p10));
                    float F = 1.0f / (1.0f + expf(-p11));
                    float O = 1.0f / (1.0f + expf(-o10));
                    float c = F * g_Cst[cidx] + I * tanhf(o11);
                    g_Cst[cidx] = c;
                    float h = O * tanhf(c);
                    hall[cidx] = h;
                    __nv_bfloat16 hh, hl; split_bf16(h, hh, hl);
                    ahi[cidx] = hh; alo[cidx] = hl;
                }
            }
        }
    }
}

// ---------------- persistent cooperative recurrence: 64 CTAs, 1 sync/step ----------------
__global__ __launch_bounds__(128, 1)
void lstm_persist(int dummy)
{
    __shared__ __align__(128) char sm[2][15360];
    cg::grid_group grid = cg::this_grid();
    (void)dummy;
    for (int s = 0; s < S_; ++s) {
        lstm_mma_body(&sm[0][0], s, blockIdx.x, threadIdx.x);
        grid.sync();
    }
}

// ---------------- fallback per-step kernel (R11-measured path) ----------------
__global__ __launch_bounds__(128)
void lstm_step_k(int s)
{
    __shared__ __align__(128) char sm[2][15360];
    lstm_mma_body(&sm[0][0], s, blockIdx.x, threadIdx.x);
}

// ---------------- tail: Hf, Cf ----------------
__global__ void tail_kernel(float* __restrict__ out, int out_size)
{
    const long YOFF = (long)SB_ * V_;
    int idx = blockIdx.x * blockDim.x + threadIdx.x;
    if ((long)out_size >= YOFF + 2L * B_ * HID_) {
        out[YOFF + idx] = g_Hall[(S_ - 1) * B_ * HID_ + idx];
        out[YOFF + B_ * HID_ + idx] = g_Cst[idx];
    }
}

// ---------------- launch ----------------
extern "C" void kernel_launch(void* const* d_in, const int* in_sizes, int n_in,
                              void* d_out, int out_size)
{
    const void*  X   = d_in[0];
    const float* H0  = (const float*)d_in[1];
    const float* C0  = (const float*)d_in[2];
    const float* emb = (const float*)d_in[3];
    const float* Wxi = (const float*)d_in[4];
    const float* Whi = (const float*)d_in[5];
    const float* bi  = (const float*)d_in[6];
    const float* Wxf = (const float*)d_in[7];
    const float* Whf = (const float*)d_in[8];
    const float* bf  = (const float*)d_in[9];
    const float* Wxo = (const float*)d_in[10];
    const float* Who = (const float*)d_in[11];
    const float* bo  = (const float*)d_in[12];
    const float* Wxc = (const float*)d_in[13];
    const float* Whc = (const float*)d_in[14];
    const float* bc  = (const float*)d_in[15];
    const float* Whq = (const float*)d_in[16];
    const float* bq  = (const float*)d_in[17];
    float* out = (float*)d_out;

    void *pXeHi, *pXeLo, *pWxTHi, *pWxTLo, *pAHi, *pALo, *pBHi, *pBLo, *pb, *pXpre;
    cudaGetSymbolAddress(&pXeHi,  g_XeHi);
    cudaGetSymbolAddress(&pXeLo,  g_XeLo);
    cudaGetSymbolAddress(&pWxTHi, g_WxTHi);
    cudaGetSymbolAddress(&pWxTLo, g_WxTLo);
    cudaGetSymbolAddress(&pAHi,   g_AHi);
    cudaGetSymbolAddress(&pALo,   g_ALo);
    cudaGetSymbolAddress(&pBHi,   g_BHi);
    cudaGetSymbolAddress(&pBLo,   g_BLo);
    cudaGetSymbolAddress(&pb,     g_bcat);
    cudaGetSymbolAddress(&pXpre,  g_Xpre);

    cudaFuncSetAttribute(gemm_mma, cudaFuncAttributeMaxDynamicSharedMemorySize, GEMM_SMEM);

    detect_kernel<<<1, 32>>>((const int*)X);
    prep_kernel<<<4096, 256>>>(Wxi, Whi, bi, Wxf, Whf, bf,
                               Wxo, Who, bo, Wxc, Whc, bc, C0, H0);
    gather_kernel<<<4096, 256>>>(X, emb);
    wq_split<<<dim3(V_ / 32, HID_ / 32), dim3(32, 8)>>>(Whq);

    // Xpre = Xe @ Wx^T + bcat   (M=4096, N=4096 gate-interleaved, K=1024)
    gemm_mma<<<dim3(SB_ / 128, G4_ / 128), 256, GEMM_SMEM>>>(
        (const __nv_bfloat16*)pXeHi, (const __nv_bfloat16*)pXeLo,
        (const __nv_bfloat16*)pWxTHi, (const __nv_bfloat16*)pWxTLo,
        (const float*)pb, (float*)pXpre, G4_);

    // recurrence: persistent cooperative HMMA (1 sync/step); fallback = per-step launches
    {
        int dummy = 0;
        void* args[1] = { (void*)&dummy };
        cudaError_t ce = cudaLaunchCooperativeKernel(
            (const void*)lstm_persist, dim3(64), dim3(128), args, (size_t)0, (cudaStream_t)0);
        if (ce != cudaSuccess) {
            cudaGetLastError();   // clear sticky error
            for (int s = 0; s < S_; ++s)
                lstm_step_k<<<64, 128>>>(s);
        }
    }

    // Y = Hall @ Whq + bq  (M=4096, N=32000, K=1024)
    gemm_mma<<<dim3(SB_ / 128, V_ / 128), 256, GEMM_SMEM>>>(
        (const __nv_bfloat16*)pAHi, (const __nv_bfloat16*)pALo,
        (const __nv_bfloat16*)pBHi, (const __nv_bfloat16*)pBLo,
        bq, out, V_);

    tail_kernel<<<128, 256>>>(out, out_size);
}

// round 16
// speedup vs baseline: 1.5965x; 1.0205x over previous
#include <cuda_runtime.h>
#include <cuda_bf16.h>
#include <math.h>

typedef unsigned long long ull;
typedef unsigned int u32;

#define E_   1024
#define HID_ 1024
#define V_   32000
#define B_   32
#define S_   128
#define SB_  4096   // S_*B_
#define G4_  4096   // 4*HID_

// ---------------- device scratch (static, no allocation) ----------------
__device__ float g_WhT[G4_ * HID_];     // [(g*HID+j)][k]  fp32, recurrence
__device__ float g_bcat[G4_];
__device__ float g_Xpre[SB_ * G4_];
__device__ float g_Hall[SB_ * HID_];
__device__ float g_Cst[B_ * HID_];
__device__ float g_Part[2][B_ * G4_];   // k-split partials
__device__ __nv_bfloat16 g_XeHi[SB_ * E_];            // embedded inputs hi/lo
__device__ __nv_bfloat16 g_XeLo[SB_ * E_];
__device__ __nv_bfloat16 g_WxTHi[G4_ * E_];           // Wx^T [g*HID+j][k] hi/lo
__device__ __nv_bfloat16 g_WxTLo[G4_ * E_];
__device__ __nv_bfloat16 g_AHi[SB_ * HID_];           // Hall hi/lo (written by reduce)
__device__ __nv_bfloat16 g_ALo[SB_ * HID_];
__device__ __nv_bfloat16 g_BHi[(size_t)V_ * HID_];    // Whq^T [n][k] hi/lo
__device__ __nv_bfloat16 g_BLo[(size_t)V_ * HID_];
__device__ int g_is64;

// ---------------- helpers ----------------
__device__ __forceinline__ u32 smem_u32(const void* p) {
    u32 a;
    asm("{ .reg .u64 t; cvta.to.shared.u64 t, %1; cvt.u32.u64 %0, t; }" : "=r"(a) : "l"(p));
    return a;
}
__device__ __forceinline__ ull gptr(const void* p) {
    ull g; asm("cvta.to.global.u64 %0, %1;" : "=l"(g) : "l"(p)); return g;
}
__device__ __forceinline__ float ldcg(const float* p) {
    float v; asm volatile("ld.global.cg.f32 %0, [%1];" : "=f"(v) : "l"(p)); return v;
}
#define CPASYNC16(dst, src) \
    asm volatile("cp.async.ca.shared.global [%0], [%1], 16;" :: "r"(dst), "l"(src))
#define CP_COMMIT()  asm volatile("cp.async.commit_group;")
#define CP_WAIT(n)   asm volatile("cp.async.wait_group %0;" :: "n"(n))

#define LDSM4(r, a) \
    asm volatile("ldmatrix.sync.aligned.m8n8.x4.shared.b16 {%0,%1,%2,%3}, [%4];" \
        : "=r"((r)[0]), "=r"((r)[1]), "=r"((r)[2]), "=r"((r)[3]) : "r"(a))

__device__ __forceinline__ void mma_bf16(float* d, const u32* a, const u32* b) {
    asm volatile("mma.sync.aligned.m16n8k16.row.col.f32.bf16.bf16.f32 "
        "{%0,%1,%2,%3}, {%4,%5,%6,%7}, {%8,%9}, {%0,%1,%2,%3};"
        : "+f"(d[0]), "+f"(d[1]), "+f"(d[2]), "+f"(d[3])
        : "r"(a[0]), "r"(a[1]), "r"(a[2]), "r"(a[3]), "r"(b[0]), "r"(b[1]));
}

__device__ __forceinline__ void split_bf16(float v, __nv_bfloat16& h, __nv_bfloat16& l) {
    h = __float2bfloat16(v);
    l = __float2bfloat16(v - __bfloat162float(h));
}

// ---------------- dtype detect ----------------
__global__ void detect_kernel(const int* __restrict__ X32)
{
    if (blockIdx.x == 0 && threadIdx.x == 0) {
        int o = 0;
#pragma unroll
        for (int i = 0; i < 32; ++i) o |= X32[2 * i + 1];
        g_is64 = (o == 0) ? 1 : 0;
    }
}

// ---------------- prep: WhT fp32, WxT bf16 hi/lo, bias concat, C copy ----------------
__global__ void prep_kernel(
    const float* __restrict__ Wxi, const float* __restrict__ Whi, const float* __restrict__ bi,
    const float* __restrict__ Wxf, const float* __restrict__ Whf, const float* __restrict__ bf,
    const float* __restrict__ Wxo, const float* __restrict__ Who, const float* __restrict__ bo,
    const float* __restrict__ Wxc, const float* __restrict__ Whc, const float* __restrict__ bc,
    const float* __restrict__ Cin)
{
    int idx = blockIdx.x * blockDim.x + threadIdx.x;
    if (idx < E_ * HID_) {
        int k = idx >> 10, j = idx & 1023;
        const float* wx[4] = { Wxi, Wxf, Wxo, Wxc };
        const float* wh[4] = { Whi, Whf, Who, Whc };
#pragma unroll
        for (int g = 0; g < 4; ++g) {
            size_t r = (size_t)(g * HID_ + j);
            float xv = wx[g][idx];
            __nv_bfloat16 h, l; split_bf16(xv, h, l);
            g_WxTHi[r * E_ + k] = h;
            g_WxTLo[r * E_ + k] = l;
            g_WhT[r * HID_ + k] = wh[g][idx];
        }
    }
    if (idx < G4_) {
        int g = idx >> 10, j = idx & 1023;
        const float* bp = (g == 0) ? bi : (g == 1) ? bf : (g == 2) ? bo : bc;
        g_bcat[idx] = bp[j];
    }
    if (idx < B_ * HID_) g_Cst[idx] = Cin[idx];
}

// ---------------- gather + bf16 split ----------------
__global__ void gather_kernel(const void* __restrict__ Xraw, const float* __restrict__ emb)
{
    int id = blockIdx.x * blockDim.x + threadIdx.x;    // SB_*E_/4
    int r  = id >> 8;
    int k4 = (id & 255) << 2;
    int s = r >> 5, b = r & 31;
    int tok;
    if (g_is64) tok = (int)((const long long*)Xraw)[b * S_ + s];
    else        tok = ((const int*)Xraw)[b * S_ + s];
    float4 v = *(const float4*)&emb[(size_t)tok * E_ + k4];
    __nv_bfloat16 h0, l0, h1, l1, h2, l2, h3, l3;
    split_bf16(v.x, h0, l0); split_bf16(v.y, h1, l1);
    split_bf16(v.z, h2, l2); split_bf16(v.w, h3, l3);
    uint2 hp, lp;
    hp.x = (u32)__bfloat16_as_ushort(h0) | ((u32)__bfloat16_as_ushort(h1) << 16);
    hp.y = (u32)__bfloat16_as_ushort(h2) | ((u32)__bfloat16_as_ushort(h3) << 16);
    lp.x = (u32)__bfloat16_as_ushort(l0) | ((u32)__bfloat16_as_ushort(l1) << 16);
    lp.y = (u32)__bfloat16_as_ushort(l2) | ((u32)__bfloat16_as_ushort(l3) << 16);
    *(uint2*)&g_XeHi[r * E_ + k4] = hp;
    *(uint2*)&g_XeLo[r * E_ + k4] = lp;
}

// ---------------- Whq transpose + bf16 split ----------------
__global__ void wq_split(const float* __restrict__ Wq)
{
    __shared__ float t[32][33];
    int n0 = blockIdx.x * 32, k0 = blockIdx.y * 32;
    int tx = threadIdx.x, ty = threadIdx.y;   // 32 x 8
#pragma unroll
    for (int i = 0; i < 4; ++i) {
        int k = k0 + ty + i * 8;
        t[ty + i * 8][tx] = Wq[(size_t)k * V_ + n0 + tx];
    }
    __syncthreads();
#pragma unroll
    for (int i = 0; i < 4; ++i) {
        int n = n0 + ty + i * 8;
        float v = t[tx][ty + i * 8];
        __nv_bfloat16 h, l; split_bf16(v, h, l);
        g_BHi[(size_t)n * HID_ + k0 + tx] = h;
        g_BLo[(size_t)n * HID_ + k0 + tx] = l;
    }
}

// ---------------- generic split-bf16 HMMA GEMM (R8-proven: 128x128, 256 thr) ----------------
#define GEMM_SMEM 81920
__global__ __launch_bounds__(256, 2)
void gemm_mma(const __nv_bfloat16* __restrict__ Ahi, const __nv_bfloat16* __restrict__ Alo,
              const __nv_bfloat16* __restrict__ Bhi, const __nv_bfloat16* __restrict__ Blo,
              const float* __restrict__ bias, float* __restrict__ C, int ldc)
{
    extern __shared__ __align__(128) char smraw[];
    const u32 sbase = smem_u32(smraw);
    const int tid = threadIdx.x;
    const int lane = tid & 31, wid = tid >> 5;
    const int wm = (wid & 3) * 32, wn = (wid >> 2) * 64;
    const size_t m0 = (size_t)blockIdx.x * 128, n0 = (size_t)blockIdx.y * 128;

    ull gsrc[4];
    gsrc[0] = gptr(Ahi + m0 * 1024);
    gsrc[1] = gptr(Alo + m0 * 1024);
    gsrc[2] = gptr(Bhi + n0 * 1024);
    gsrc[3] = gptr(Blo + n0 * 1024);

    const int lrow = tid >> 2;
    const int lc16 = (tid & 3) * 16;

    auto load_chunk = [&](int ch, int buf) {
        const u32 bb = sbase + buf * 40960;
        const ull srcoff = (ull)ch * 64;
#pragma unroll
        for (int mat = 0; mat < 4; ++mat) {
            const ull src = gsrc[mat] + srcoff;
            const u32 dst = bb + mat * 10240;
#pragma unroll
            for (int j = 0; j < 2; ++j) {
                int row = lrow + j * 64;
                CPASYNC16(dst + row * 80 + lc16, (const void*)(src + (ull)row * 2048 + lc16));
            }
        }
        CP_COMMIT();
    };

    float acc[2][8][4];
#pragma unroll
    for (int mf = 0; mf < 2; ++mf)
#pragma unroll
        for (int nf = 0; nf < 8; ++nf)
#pragma unroll
            for (int q = 0; q < 4; ++q) acc[mf][nf][q] = 0.0f;

    load_chunk(0, 0);

    for (int ch = 0; ch < 32; ++ch) {
        if (ch < 31) { load_chunk(ch + 1, (ch + 1) & 1); CP_WAIT(1); }
        else         { CP_WAIT(0); }
        __syncthreads();
        const u32 bb = sbase + (ch & 1) * 40960;
#pragma unroll
        for (int ks = 0; ks < 2; ++ks) {
            u32 ah[8], al[8];
            const u32 arow = wm + (lane & 15);
            const u32 acol = ks * 32 + ((lane >> 4) << 4);
            const u32 a0 = bb + arow * 80 + acol;
            const u32 a1 = bb + (arow + 16) * 80 + acol;
            LDSM4(&ah[0], a0); LDSM4(&ah[4], a1);
            LDSM4(&al[0], a0 + 10240); LDSM4(&al[4], a1 + 10240);
#pragma unroll
            for (int p = 0; p < 4; ++p) {
                u32 bh[4], bl[4];
                const u32 brow = wn + p * 16 + (lane & 7) + ((lane & 16) ? 8 : 0);
                const u32 bcol = ks * 32 + ((lane & 8) ? 16 : 0);
                const u32 ba = bb + 20480 + brow * 80 + bcol;
                LDSM4(bh, ba); LDSM4(bl, ba + 10240);
#pragma unroll
                for (int mf = 0; mf < 2; ++mf)
#pragma unroll
                    for (int sub = 0; sub < 2; ++sub) {
                        float* d = acc[mf][p * 2 + sub];
                        mma_bf16(d, &ah[mf * 4], &bh[sub * 2]);   // hi*hi
                        mma_bf16(d, &ah[mf * 4], &bl[sub * 2]);   // hi*lo
                        mma_bf16(d, &al[mf * 4], &bh[sub * 2]);   // lo*hi
                    }
            }
        }
        __syncthreads();
    }

    const int r0 = lane >> 2, cp2 = (lane & 3) * 2;
#pragma unroll
    for (int mf = 0; mf < 2; ++mf) {
        const size_t row = m0 + wm + mf * 16 + r0;
#pragma unroll
        for (int nf = 0; nf < 8; ++nf) {
            const size_t col = n0 + wn + nf * 8 + cp2;
            const float b0 = bias[col], b1 = bias[col + 1];
            float2 v0 = { acc[mf][nf][0] + b0, acc[mf][nf][1] + b1 };
            float2 v1 = { acc[mf][nf][2] + b0, acc[mf][nf][3] + b1 };
            *(float2*)&C[row * (size_t)ldc + col] = v0;
            *(float2*)&C[(row + 8) * (size_t)ldc + col] = v1;
        }
    }
}

// ================= recurrence phase kernels (R8/R13-measured bodies) =================
#define LSTM_SMEM ((2 * 32 * 68 + 2 * 64 * 68) * 4)

__global__ __launch_bounds__(128)
void lstm_gemm_k(const float* __restrict__ Hin, int s)
{
    extern __shared__ __align__(128) float sm[];
    float* hsm = sm;                 // [2][32*68]
    float* wsm = sm + 2 * 32 * 68;   // [2][64*68]

    const int tid = threadIdx.x;
    const int tx = tid & 15, ty = tid >> 4;
    const int ct = blockIdx.x & 63, kh = blockIdx.x >> 6;
    const int c0 = ct * 64, kbase = kh * 512;
    const float* hprev = (s == 0) ? Hin : (g_Hall + (size_t)(s - 1) * B_ * HID_);

    float4 hreg[4], wreg[8];
#pragma unroll
    for (int i = 0; i < 4; ++i) {
        int idx = i * 128 + tid; int row = idx >> 4, seg = (idx & 15) << 2;
        hreg[i] = *(const float4*)&hprev[row * HID_ + kbase + seg];
    }
#pragma unroll
    for (int i = 0; i < 8; ++i) {
        int idx = i * 128 + tid; int row = idx >> 4, seg = (idx & 15) << 2;
        wreg[i] = *(const float4*)&g_WhT[(size_t)(c0 + row) * HID_ + kbase + seg];
    }
#pragma unroll
    for (int i = 0; i < 4; ++i) {
        int idx = i * 128 + tid; int row = idx >> 4, seg = (idx & 15) << 2;
        *(float4*)&hsm[row * 68 + seg] = hreg[i];
    }
#pragma unroll
    for (int i = 0; i < 8; ++i) {
        int idx = i * 128 + tid; int row = idx >> 4, seg = (idx & 15) << 2;
        *(float4*)&wsm[row * 68 + seg] = wreg[i];
    }
    __syncthreads();

    float acc[4][4];
#pragma unroll
    for (int a = 0; a < 4; ++a)
#pragma unroll
        for (int b = 0; b < 4; ++b) acc[a][b] = 0.0f;

    for (int ch = 0; ch < 8; ++ch) {
        const int cur = ch & 1;
        if (ch < 7) {
            const int k0 = kbase + (ch + 1) * 64;
#pragma unroll
            for (int i = 0; i < 4; ++i) {
                int idx = i * 128 + tid; int row = idx >> 4, seg = (idx & 15) << 2;
                hreg[i] = *(const float4*)&hprev[row * HID_ + k0 + seg];
            }
#pragma unroll
            for (int i = 0; i < 8; ++i) {
                int idx = i * 128 + tid; int row = idx >> 4, seg = (idx & 15) << 2;
                wreg[i] = *(const float4*)&g_WhT[(size_t)(c0 + row) * HID_ + k0 + seg];
            }
        }
        const float* hb = hsm + cur * (32 * 68);
        const float* wb = wsm + cur * (64 * 68);
#pragma unroll
        for (int kk = 0; kk < 64; kk += 4) {
            float4 hv[4], wv[4];
#pragma unroll
            for (int bb = 0; bb < 4; ++bb) hv[bb] = *(const float4*)&hb[(ty * 4 + bb) * 68 + kk];
#pragma unroll
            for (int cc = 0; cc < 4; ++cc) wv[cc] = *(const float4*)&wb[(tx + cc * 16) * 68 + kk];
#pragma unroll
            for (int bb = 0; bb < 4; ++bb)
#pragma unroll
                for (int cc = 0; cc < 4; ++cc) {
                    acc[bb][cc] = fmaf(hv[bb].x, wv[cc].x, acc[bb][cc]);
                    acc[bb][cc] = fmaf(hv[bb].y, wv[cc].y, acc[bb][cc]);
                    acc[bb][cc] = fmaf(hv[bb].z, wv[cc].z, acc[bb][cc]);
                    acc[bb][cc] = fmaf(hv[bb].w, wv[cc].w, acc[bb][cc]);
                }
        }
        __syncthreads();
        if (ch < 7) {
            float* hn = hsm + (cur ^ 1) * (32 * 68);
            float* wn = wsm + (cur ^ 1) * (64 * 68);
#pragma unroll
            for (int i = 0; i < 4; ++i) {
                int idx = i * 128 + tid; int row = idx >> 4, seg = (idx & 15) << 2;
                *(float4*)&hn[row * 68 + seg] = hreg[i];
            }
#pragma unroll
            for (int i = 0; i < 8; ++i) {
                int idx = i * 128 + tid; int row = idx >> 4, seg = (idx & 15) << 2;
                *(float4*)&wn[row * 68 + seg] = wreg[i];
            }
            __syncthreads();
        }
    }

#pragma unroll
    for (int bb = 0; bb < 4; ++bb)
#pragma unroll
        for (int cc = 0; cc < 4; ++cc)
            g_Part[kh][(ty * 4 + bb) * G4_ + c0 + tx + cc * 16] = acc[bb][cc];
}

__global__ void lstm_reduce_k(int s)
{
    int idx = blockIdx.x * 256 + threadIdx.x;   // grid 128, block 256
    const int b = idx >> 10, j = idx & 1023;
    const float* xp = g_Xpre + (size_t)(s * B_ + b) * G4_;
    const int pb = b * G4_ + j;
    float p0 = xp[j]        + ldcg(&g_Part[0][pb])        + ldcg(&g_Part[1][pb]);
    float p1 = xp[1024 + j] + ldcg(&g_Part[0][pb + 1024]) + ldcg(&g_Part[1][pb + 1024]);
    float p2 = xp[2048 + j] + ldcg(&g_Part[0][pb + 2048]) + ldcg(&g_Part[1][pb + 2048]);
    float p3 = xp[3072 + j] + ldcg(&g_Part[0][pb + 3072]) + ldcg(&g_Part[1][pb + 3072]);
    float I = 1.0f / (1.0f + expf(-p0));
    float F = 1.0f / (1.0f + expf(-p1));
    float O = 1.0f / (1.0f + expf(-p2));
    float Ct = tanhf(p3);
    float c = F * g_Cst[idx] + I * Ct;
    g_Cst[idx] = c;
    float h = O * tanhf(c);
    const size_t hidx = (size_t)s * B_ * HID_ + idx;
    g_Hall[hidx] = h;
    __nv_bfloat16 hh, hl; split_bf16(h, hh, hl);
    g_AHi[hidx] = hh;
    g_ALo[hidx] = hl;
}

// ---------------- tail: Hf, Cf ----------------
__global__ void tail_kernel(float* __restrict__ out, int out_size)
{
    const long YOFF = (long)SB_ * V_;
    int idx = blockIdx.x * blockDim.x + threadIdx.x;
    if ((long)out_size >= YOFF + 2L * B_ * HID_) {
        out[YOFF + idx] = g_Hall[(S_ - 1) * B_ * HID_ + idx];
        out[YOFF + B_ * HID_ + idx] = g_Cst[idx];
    }
}

// ---------------- launch ----------------
extern "C" void kernel_launch(void* const* d_in, const int* in_sizes, int n_in,
                              void* d_out, int out_size)
{
    const void*  X   = d_in[0];
    const float* H0  = (const float*)d_in[1];
    const float* C0  = (const float*)d_in[2];
    const float* emb = (const float*)d_in[3];
    const float* Wxi = (const float*)d_in[4];
    const float* Whi = (const float*)d_in[5];
    const float* bi  = (const float*)d_in[6];
    const float* Wxf = (const float*)d_in[7];
    const float* Whf = (const float*)d_in[8];
    const float* bf  = (const float*)d_in[9];
    const float* Wxo = (const float*)d_in[10];
    const float* Who = (const float*)d_in[11];
    const float* bo  = (const float*)d_in[12];
    const float* Wxc = (const float*)d_in[13];
    const float* Whc = (const float*)d_in[14];
    const float* bc  = (const float*)d_in[15];
    const float* Whq = (const float*)d_in[16];
    const float* bq  = (const float*)d_in[17];
    float* out = (float*)d_out;

    void *pXeHi, *pXeLo, *pWxTHi, *pWxTLo, *pAHi, *pALo, *pBHi, *pBLo, *pb, *pXpre;
    cudaGetSymbolAddress(&pXeHi,  g_XeHi);
    cudaGetSymbolAddress(&pXeLo,  g_XeLo);
    cudaGetSymbolAddress(&pWxTHi, g_WxTHi);
    cudaGetSymbolAddress(&pWxTLo, g_WxTLo);
    cudaGetSymbolAddress(&pAHi,   g_AHi);
    cudaGetSymbolAddress(&pALo,   g_ALo);
    cudaGetSymbolAddress(&pBHi,   g_BHi);
    cudaGetSymbolAddress(&pBLo,   g_BLo);
    cudaGetSymbolAddress(&pb,     g_bcat);
    cudaGetSymbolAddress(&pXpre,  g_Xpre);

    cudaFuncSetAttribute(gemm_mma,    cudaFuncAttributeMaxDynamicSharedMemorySize, GEMM_SMEM);
    cudaFuncSetAttribute(lstm_gemm_k, cudaFuncAttributeMaxDynamicSharedMemorySize, LSTM_SMEM);

    // one-time side stream + events (host objects; created outside capture on first call)
    static cudaStream_t s1 = nullptr;
    static cudaEvent_t evStep[32];
    static cudaEvent_t evJoin;
    if (s1 == nullptr) {
        cudaStreamCreateWithFlags(&s1, cudaStreamNonBlocking);
        for (int m = 0; m < 32; ++m)
            cudaEventCreateWithFlags(&evStep[m], cudaEventDisableTiming);
        cudaEventCreateWithFlags(&evJoin, cudaEventDisableTiming);
    }

    detect_kernel<<<1, 32>>>((const int*)X);
    prep_kernel<<<4096, 256>>>(Wxi, Whi, bi, Wxf, Whf, bf,
                               Wxo, Who, bo, Wxc, Whc, bc, C0);
    gather_kernel<<<4096, 256>>>(X, emb);
    wq_split<<<dim3(V_ / 32, HID_ / 32), dim3(32, 8)>>>(Whq);

    // Xpre = Xe @ Wx^T + bcat   (M=4096, N=4096, K=1024)
    gemm_mma<<<dim3(SB_ / 128, G4_ / 128), 256, GEMM_SMEM>>>(
        (const __nv_bfloat16*)pXeHi, (const __nv_bfloat16*)pXeLo,
        (const __nv_bfloat16*)pWxTHi, (const __nv_bfloat16*)pWxTLo,
        (const float*)pb, (float*)pXpre, G4_);

    // recurrence on stream 0, projection m-slices overlapped on stream 1
    for (int m = 0; m < 32; ++m) {
        for (int s = 4 * m; s < 4 * m + 4; ++s) {
            lstm_gemm_k<<<128, 128, LSTM_SMEM>>>(H0, s);
            lstm_reduce_k<<<128, 256>>>(s);
        }
        cudaEventRecord(evStep[m], 0);
        cudaStreamWaitEvent(s1, evStep[m], 0);
        const size_t m0 = (size_t)m * 128;
        gemm_mma<<<dim3(1, V_ / 128), 256, GEMM_SMEM, s1>>>(
            (const __nv_bfloat16*)pAHi + m0 * HID_,
            (const __nv_bfloat16*)pALo + m0 * HID_,
            (const __nv_bfloat16*)pBHi, (const __nv_bfloat16*)pBLo,
            bq, out + m0 * V_, V_);
    }
    cudaEventRecord(evJoin, s1);
    cudaStreamWaitEvent(0, evJoin, 0);

    tail_kernel<<<128, 256>>>(out, out_size);
}

// round 17
// speedup vs baseline: 2.3090x; 1.4463x over previous
#include <cuda_runtime.h>
#include <cuda_bf16.h>
#include <cuda_fp16.h>
#include <cooperative_groups.h>
#include <math.h>

namespace cg = cooperative_groups;

typedef unsigned long long ull;
typedef unsigned int u32;

#define E_   1024
#define HID_ 1024
#define V_   32000
#define B_   32
#define S_   128
#define SB_  4096   // S_*B_
#define G4_  4096   // 4*HID_

// ---------------- device scratch (static, no allocation) ----------------
__device__ float g_WhT[G4_ * HID_];     // [(g*HID+j)][k]  fp32, recurrence
__device__ float g_bcat[G4_];
__device__ float g_Xpre[SB_ * G4_];
__device__ float g_Hall[SB_ * HID_];
__device__ float g_Cst[B_ * HID_];
__device__ float g_Part[2][B_ * G4_];   // k-split partials
__device__ __nv_bfloat16 g_XeHi[SB_ * E_];            // embedded inputs hi/lo
__device__ __nv_bfloat16 g_XeLo[SB_ * E_];
__device__ __nv_bfloat16 g_WxTHi[G4_ * E_];           // Wx^T [g*HID+j][k] hi/lo
__device__ __nv_bfloat16 g_WxTLo[G4_ * E_];
__device__ __half g_PA[SB_ * HID_];                   // Hall fp16 (projection A)
__device__ __half g_PB[(size_t)V_ * HID_];            // Whq^T [n][k] fp16 (projection B)
__device__ int g_is64;

// ---------------- helpers ----------------
__device__ __forceinline__ u32 smem_u32(const void* p) {
    u32 a;
    asm("{ .reg .u64 t; cvta.to.shared.u64 t, %1; cvt.u32.u64 %0, t; }" : "=r"(a) : "l"(p));
    return a;
}
__device__ __forceinline__ ull gptr(const void* p) {
    ull g; asm("cvta.to.global.u64 %0, %1;" : "=l"(g) : "l"(p)); return g;
}
__device__ __forceinline__ float ldcg(const float* p) {
    float v; asm volatile("ld.global.cg.f32 %0, [%1];" : "=f"(v) : "l"(p)); return v;
}
#define CPASYNC16(dst, src) \
    asm volatile("cp.async.ca.shared.global [%0], [%1], 16;" :: "r"(dst), "l"(src))
#define CP_COMMIT()  asm volatile("cp.async.commit_group;")
#define CP_WAIT(n)   asm volatile("cp.async.wait_group %0;" :: "n"(n))

#define LDSM4(r, a) \
    asm volatile("ldmatrix.sync.aligned.m8n8.x4.shared.b16 {%0,%1,%2,%3}, [%4];" \
        : "=r"((r)[0]), "=r"((r)[1]), "=r"((r)[2]), "=r"((r)[3]) : "r"(a))

__device__ __forceinline__ void mma_bf16(float* d, const u32* a, const u32* b) {
    asm volatile("mma.sync.aligned.m16n8k16.row.col.f32.bf16.bf16.f32 "
        "{%0,%1,%2,%3}, {%4,%5,%6,%7}, {%8,%9}, {%0,%1,%2,%3};"
        : "+f"(d[0]), "+f"(d[1]), "+f"(d[2]), "+f"(d[3])
        : "r"(a[0]), "r"(a[1]), "r"(a[2]), "r"(a[3]), "r"(b[0]), "r"(b[1]));
}
__device__ __forceinline__ void mma_fp16(float* d, const u32* a, const u32* b) {
    asm volatile("mma.sync.aligned.m16n8k16.row.col.f32.f16.f16.f32 "
        "{%0,%1,%2,%3}, {%4,%5,%6,%7}, {%8,%9}, {%0,%1,%2,%3};"
        : "+f"(d[0]), "+f"(d[1]), "+f"(d[2]), "+f"(d[3])
        : "r"(a[0]), "r"(a[1]), "r"(a[2]), "r"(a[3]), "r"(b[0]), "r"(b[1]));
}

__device__ __forceinline__ void split_bf16(float v, __nv_bfloat16& h, __nv_bfloat16& l) {
    h = __float2bfloat16(v);
    l = __float2bfloat16(v - __bfloat162float(h));
}

// ---------------- dtype detect ----------------
__global__ void detect_kernel(const int* __restrict__ X32)
{
    if (blockIdx.x == 0 && threadIdx.x == 0) {
        int o = 0;
#pragma unroll
        for (int i = 0; i < 32; ++i) o |= X32[2 * i + 1];
        g_is64 = (o == 0) ? 1 : 0;
    }
}

// ---------------- prep: WhT fp32, WxT bf16 hi/lo, bias concat, C copy ----------------
__global__ void prep_kernel(
    const float* __restrict__ Wxi, const float* __restrict__ Whi, const float* __restrict__ bi,
    const float* __restrict__ Wxf, const float* __restrict__ Whf, const float* __restrict__ bf,
    const float* __restrict__ Wxo, const float* __restrict__ Who, const float* __restrict__ bo,
    const float* __restrict__ Wxc, const float* __restrict__ Whc, const float* __restrict__ bc,
    const float* __restrict__ Cin)
{
    int idx = blockIdx.x * blockDim.x + threadIdx.x;
    if (idx < E_ * HID_) {
        int k = idx >> 10, j = idx & 1023;
        const float* wx[4] = { Wxi, Wxf, Wxo, Wxc };
        const float* wh[4] = { Whi, Whf, Who, Whc };
#pragma unroll
        for (int g = 0; g < 4; ++g) {
            size_t r = (size_t)(g * HID_ + j);
            float xv = wx[g][idx];
            __nv_bfloat16 h, l; split_bf16(xv, h, l);
            g_WxTHi[r * E_ + k] = h;
            g_WxTLo[r * E_ + k] = l;
            g_WhT[r * HID_ + k] = wh[g][idx];
        }
    }
    if (idx < G4_) {
        int g = idx >> 10, j = idx & 1023;
        const float* bp = (g == 0) ? bi : (g == 1) ? bf : (g == 2) ? bo : bc;
        g_bcat[idx] = bp[j];
    }
    if (idx < B_ * HID_) g_Cst[idx] = Cin[idx];
}

// ---------------- gather + bf16 split ----------------
__global__ void gather_kernel(const void* __restrict__ Xraw, const float* __restrict__ emb)
{
    int id = blockIdx.x * blockDim.x + threadIdx.x;    // SB_*E_/4
    int r  = id >> 8;
    int k4 = (id & 255) << 2;
    int s = r >> 5, b = r & 31;
    int tok;
    if (g_is64) tok = (int)((const long long*)Xraw)[b * S_ + s];
    else        tok = ((const int*)Xraw)[b * S_ + s];
    float4 v = *(const float4*)&emb[(size_t)tok * E_ + k4];
    __nv_bfloat16 h0, l0, h1, l1, h2, l2, h3, l3;
    split_bf16(v.x, h0, l0); split_bf16(v.y, h1, l1);
    split_bf16(v.z, h2, l2); split_bf16(v.w, h3, l3);
    uint2 hp, lp;
    hp.x = (u32)__bfloat16_as_ushort(h0) | ((u32)__bfloat16_as_ushort(h1) << 16);
    hp.y = (u32)__bfloat16_as_ushort(h2) | ((u32)__bfloat16_as_ushort(h3) << 16);
    lp.x = (u32)__bfloat16_as_ushort(l0) | ((u32)__bfloat16_as_ushort(l1) << 16);
    lp.y = (u32)__bfloat16_as_ushort(l2) | ((u32)__bfloat16_as_ushort(l3) << 16);
    *(uint2*)&g_XeHi[r * E_ + k4] = hp;
    *(uint2*)&g_XeLo[r * E_ + k4] = lp;
}

// ---------------- Whq transpose + fp16 convert ----------------
__global__ void wq_split(const float* __restrict__ Wq)
{
    __shared__ float t[32][33];
    int n0 = blockIdx.x * 32, k0 = blockIdx.y * 32;
    int tx = threadIdx.x, ty = threadIdx.y;   // 32 x 8
#pragma unroll
    for (int i = 0; i < 4; ++i) {
        int k = k0 + ty + i * 8;
        t[ty + i * 8][tx] = Wq[(size_t)k * V_ + n0 + tx];
    }
    __syncthreads();
#pragma unroll
    for (int i = 0; i < 4; ++i) {
        int n = n0 + ty + i * 8;
        g_PB[(size_t)n * HID_ + k0 + tx] = __float2half(t[tx][ty + i * 8]);
    }
}

// ---------------- generic split-bf16 HMMA GEMM (R8-proven: 128x128, 256 thr) ----------------
#define GEMM_SMEM 81920
__global__ __launch_bounds__(256, 2)
void gemm_mma(const __nv_bfloat16* __restrict__ Ahi, const __nv_bfloat16* __restrict__ Alo,
              const __nv_bfloat16* __restrict__ Bhi, const __nv_bfloat16* __restrict__ Blo,
              const float* __restrict__ bias, float* __restrict__ C, int ldc)
{
    extern __shared__ __align__(128) char smraw[];
    const u32 sbase = smem_u32(smraw);
    const int tid = threadIdx.x;
    const int lane = tid & 31, wid = tid >> 5;
    const int wm = (wid & 3) * 32, wn = (wid >> 2) * 64;
    const size_t m0 = (size_t)blockIdx.x * 128, n0 = (size_t)blockIdx.y * 128;

    ull gsrc[4];
    gsrc[0] = gptr(Ahi + m0 * 1024);
    gsrc[1] = gptr(Alo + m0 * 1024);
    gsrc[2] = gptr(Bhi + n0 * 1024);
    gsrc[3] = gptr(Blo + n0 * 1024);

    const int lrow = tid >> 2;
    const int lc16 = (tid & 3) * 16;

    auto load_chunk = [&](int ch, int buf) {
        const u32 bb = sbase + buf * 40960;
        const ull srcoff = (ull)ch * 64;
#pragma unroll
        for (int mat = 0; mat < 4; ++mat) {
            const ull src = gsrc[mat] + srcoff;
            const u32 dst = bb + mat * 10240;
#pragma unroll
            for (int j = 0; j < 2; ++j) {
                int row = lrow + j * 64;
                CPASYNC16(dst + row * 80 + lc16, (const void*)(src + (ull)row * 2048 + lc16));
            }
        }
        CP_COMMIT();
    };

    float acc[2][8][4];
#pragma unroll
    for (int mf = 0; mf < 2; ++mf)
#pragma unroll
        for (int nf = 0; nf < 8; ++nf)
#pragma unroll
            for (int q = 0; q < 4; ++q) acc[mf][nf][q] = 0.0f;

    load_chunk(0, 0);

    for (int ch = 0; ch < 32; ++ch) {
        if (ch < 31) { load_chunk(ch + 1, (ch + 1) & 1); CP_WAIT(1); }
        else         { CP_WAIT(0); }
        __syncthreads();
        const u32 bb = sbase + (ch & 1) * 40960;
#pragma unroll
        for (int ks = 0; ks < 2; ++ks) {
            u32 ah[8], al[8];
            const u32 arow = wm + (lane & 15);
            const u32 acol = ks * 32 + ((lane >> 4) << 4);
            const u32 a0 = bb + arow * 80 + acol;
            const u32 a1 = bb + (arow + 16) * 80 + acol;
            LDSM4(&ah[0], a0); LDSM4(&ah[4], a1);
            LDSM4(&al[0], a0 + 10240); LDSM4(&al[4], a1 + 10240);
#pragma unroll
            for (int p = 0; p < 4; ++p) {
                u32 bh[4], bl[4];
                const u32 brow = wn + p * 16 + (lane & 7) + ((lane & 16) ? 8 : 0);
                const u32 bcol = ks * 32 + ((lane & 8) ? 16 : 0);
                const u32 ba = bb + 20480 + brow * 80 + bcol;
                LDSM4(bh, ba); LDSM4(bl, ba + 10240);
#pragma unroll
                for (int mf = 0; mf < 2; ++mf)
#pragma unroll
                    for (int sub = 0; sub < 2; ++sub) {
                        float* d = acc[mf][p * 2 + sub];
                        mma_bf16(d, &ah[mf * 4], &bh[sub * 2]);   // hi*hi
                        mma_bf16(d, &ah[mf * 4], &bl[sub * 2]);   // hi*lo
                        mma_bf16(d, &al[mf * 4], &bh[sub * 2]);   // lo*hi
                    }
            }
        }
        __syncthreads();
    }

    const int r0 = lane >> 2, cp2 = (lane & 3) * 2;
#pragma unroll
    for (int mf = 0; mf < 2; ++mf) {
        const size_t row = m0 + wm + mf * 16 + r0;
#pragma unroll
        for (int nf = 0; nf < 8; ++nf) {
            const size_t col = n0 + wn + nf * 8 + cp2;
            const float b0 = bias[col], b1 = bias[col + 1];
            float2 v0 = { acc[mf][nf][0] + b0, acc[mf][nf][1] + b1 };
            float2 v1 = { acc[mf][nf][2] + b0, acc[mf][nf][3] + b1 };
            *(float2*)&C[row * (size_t)ldc + col] = v0;
            *(float2*)&C[(row + 8) * (size_t)ldc + col] = v1;
        }
    }
}

// ---------------- single-pass fp16 HMMA GEMM (projection) ----------------
// Same tile/fragment machinery as gemm_mma, 2 matrices, 1 MMA per fragment pair.
#define GEMMH_SMEM 40960   // 2 buffers * 2 matrices * 128 rows * 80 B
__global__ __launch_bounds__(256, 2)
void gemm_fp16(const __half* __restrict__ A, const __half* __restrict__ B,
               const float* __restrict__ bias, float* __restrict__ C, int ldc)
{
    extern __shared__ __align__(128) char smraw[];
    const u32 sbase = smem_u32(smraw);
    const int tid = threadIdx.x;
    const int lane = tid & 31, wid = tid >> 5;
    const int wm = (wid & 3) * 32, wn = (wid >> 2) * 64;
    const size_t m0 = (size_t)blockIdx.x * 128, n0 = (size_t)blockIdx.y * 128;

    ull gsrc[2];
    gsrc[0] = gptr(A + m0 * 1024);
    gsrc[1] = gptr(B + n0 * 1024);

    const int lrow = tid >> 2;
    const int lc16 = (tid & 3) * 16;

    auto load_chunk = [&](int ch, int buf) {
        const u32 bb = sbase + buf * 20480;
        const ull srcoff = (ull)ch * 64;
#pragma unroll
        for (int mat = 0; mat < 2; ++mat) {
            const ull src = gsrc[mat] + srcoff;
            const u32 dst = bb + mat * 10240;
#pragma unroll
            for (int j = 0; j < 2; ++j) {
                int row = lrow + j * 64;
                CPASYNC16(dst + row * 80 + lc16, (const void*)(src + (ull)row * 2048 + lc16));
            }
        }
        CP_COMMIT();
    };

    float acc[2][8][4];
#pragma unroll
    for (int mf = 0; mf < 2; ++mf)
#pragma unroll
        for (int nf = 0; nf < 8; ++nf)
#pragma unroll
            for (int q = 0; q < 4; ++q) acc[mf][nf][q] = 0.0f;

    load_chunk(0, 0);

    for (int ch = 0; ch < 32; ++ch) {
        if (ch < 31) { load_chunk(ch + 1, (ch + 1) & 1); CP_WAIT(1); }
        else         { CP_WAIT(0); }
        __syncthreads();
        const u32 bb = sbase + (ch & 1) * 20480;
#pragma unroll
        for (int ks = 0; ks < 2; ++ks) {
            u32 ah[8];
            const u32 arow = wm + (lane & 15);
            const u32 acol = ks * 32 + ((lane >> 4) << 4);
            LDSM4(&ah[0], bb + arow * 80 + acol);
            LDSM4(&ah[4], bb + (arow + 16) * 80 + acol);
#pragma unroll
            for (int p = 0; p < 4; ++p) {
                u32 bh[4];
                const u32 brow = wn + p * 16 + (lane & 7) + ((lane & 16) ? 8 : 0);
                const u32 bcol = ks * 32 + ((lane & 8) ? 16 : 0);
                LDSM4(bh, bb + 10240 + brow * 80 + bcol);
#pragma unroll
                for (int mf = 0; mf < 2; ++mf)
#pragma unroll
                    for (int sub = 0; sub < 2; ++sub)
                        mma_fp16(acc[mf][p * 2 + sub], &ah[mf * 4], &bh[sub * 2]);
            }
        }
        __syncthreads();
    }

    const int r0 = lane >> 2, cp2 = (lane & 3) * 2;
#pragma unroll
    for (int mf = 0; mf < 2; ++mf) {
        const size_t row = m0 + wm + mf * 16 + r0;
#pragma unroll
        for (int nf = 0; nf < 8; ++nf) {
            const size_t col = n0 + wn + nf * 8 + cp2;
            const float b0 = bias[col], b1 = bias[col + 1];
            float2 v0 = { acc[mf][nf][0] + b0, acc[mf][nf][1] + b1 };
            float2 v1 = { acc[mf][nf][2] + b0, acc[mf][nf][3] + b1 };
            *(float2*)&C[row * (size_t)ldc + col] = v0;
            *(float2*)&C[(row + 8) * (size_t)ldc + col] = v1;
        }
    }
}

// ================= recurrence phase bodies (R13-measured) =================
#define LSTM_SMEM ((2 * 32 * 68 + 2 * 64 * 68) * 4)

__device__ __forceinline__ void lstm_phaseA(float* hsm, float* wsm, const float* hprev,
                                            int blk, int tid)
{
    const int tx = tid & 15, ty = tid >> 4;
    const int ct = blk & 63, kh = blk >> 6;
    const int c0 = ct * 64, kbase = kh * 512;

    float4 hreg[4], wreg[8];
#pragma unroll
    for (int i = 0; i < 4; ++i) {
        int idx = i * 128 + tid; int row = idx >> 4, seg = (idx & 15) << 2;
        hreg[i] = *(const float4*)&hprev[row * HID_ + kbase + seg];
    }
#pragma unroll
    for (int i = 0; i < 8; ++i) {
        int idx = i * 128 + tid; int row = idx >> 4, seg = (idx & 15) << 2;
        wreg[i] = *(const float4*)&g_WhT[(size_t)(c0 + row) * HID_ + kbase + seg];
    }
#pragma unroll
    for (int i = 0; i < 4; ++i) {
        int idx = i * 128 + tid; int row = idx >> 4, seg = (idx & 15) << 2;
        *(float4*)&hsm[row * 68 + seg] = hreg[i];
    }
#pragma unroll
    for (int i = 0; i < 8; ++i) {
        int idx = i * 128 + tid; int row = idx >> 4, seg = (idx & 15) << 2;
        *(float4*)&wsm[row * 68 + seg] = wreg[i];
    }
    __syncthreads();

    float acc[4][4];
#pragma unroll
    for (int a = 0; a < 4; ++a)
#pragma unroll
        for (int b = 0; b < 4; ++b) acc[a][b] = 0.0f;

    for (int ch = 0; ch < 8; ++ch) {
        const int cur = ch & 1;
        if (ch < 7) {
            const int k0 = kbase + (ch + 1) * 64;
#pragma unroll
            for (int i = 0; i < 4; ++i) {
                int idx = i * 128 + tid; int row = idx >> 4, seg = (idx & 15) << 2;
                hreg[i] = *(const float4*)&hprev[row * HID_ + k0 + seg];
            }
#pragma unroll
            for (int i = 0; i < 8; ++i) {
                int idx = i * 128 + tid; int row = idx >> 4, seg = (idx & 15) << 2;
                wreg[i] = *(const float4*)&g_WhT[(size_t)(c0 + row) * HID_ + k0 + seg];
            }
        }
        const float* hb = hsm + cur * (32 * 68);
        const float* wb = wsm + cur * (64 * 68);
#pragma unroll
        for (int kk = 0; kk < 64; kk += 4) {
            float4 hv[4], wv[4];
#pragma unroll
            for (int bb = 0; bb < 4; ++bb) hv[bb] = *(const float4*)&hb[(ty * 4 + bb) * 68 + kk];
#pragma unroll
            for (int cc = 0; cc < 4; ++cc) wv[cc] = *(const float4*)&wb[(tx + cc * 16) * 68 + kk];
#pragma unroll
            for (int bb = 0; bb < 4; ++bb)
#pragma unroll
                for (int cc = 0; cc < 4; ++cc) {
                    acc[bb][cc] = fmaf(hv[bb].x, wv[cc].x, acc[bb][cc]);
                    acc[bb][cc] = fmaf(hv[bb].y, wv[cc].y, acc[bb][cc]);
                    acc[bb][cc] = fmaf(hv[bb].z, wv[cc].z, acc[bb][cc]);
                    acc[bb][cc] = fmaf(hv[bb].w, wv[cc].w, acc[bb][cc]);
                }
        }
        __syncthreads();
        if (ch < 7) {
            float* hn = hsm + (cur ^ 1) * (32 * 68);
            float* wn = wsm + (cur ^ 1) * (64 * 68);
#pragma unroll
            for (int i = 0; i < 4; ++i) {
                int idx = i * 128 + tid; int row = idx >> 4, seg = (idx & 15) << 2;
                *(float4*)&hn[row * 68 + seg] = hreg[i];
            }
#pragma unroll
            for (int i = 0; i < 8; ++i) {
                int idx = i * 128 + tid; int row = idx >> 4, seg = (idx & 15) << 2;
                *(float4*)&wn[row * 68 + seg] = wreg[i];
            }
            __syncthreads();
        }
    }

#pragma unroll
    for (int bb = 0; bb < 4; ++bb)
#pragma unroll
        for (int cc = 0; cc < 4; ++cc)
            g_Part[kh][(ty * 4 + bb) * G4_ + c0 + tx + cc * 16] = acc[bb][cc];
}

__device__ __forceinline__ void lstm_phaseB_elem(int s, int idx)
{
    const int b = idx >> 10, j = idx & 1023;
    const float* xp = g_Xpre + (size_t)(s * B_ + b) * G4_;
    const int pb = b * G4_ + j;
    float p0 = xp[j]        + ldcg(&g_Part[0][pb])        + ldcg(&g_Part[1][pb]);
    float p1 = xp[1024 + j] + ldcg(&g_Part[0][pb + 1024]) + ldcg(&g_Part[1][pb + 1024]);
    float p2 = xp[2048 + j] + ldcg(&g_Part[0][pb + 2048]) + ldcg(&g_Part[1][pb + 2048]);
    float p3 = xp[3072 + j] + ldcg(&g_Part[0][pb + 3072]) + ldcg(&g_Part[1][pb + 3072]);
    float I = 1.0f / (1.0f + expf(-p0));
    float F = 1.0f / (1.0f + expf(-p1));
    float O = 1.0f / (1.0f + expf(-p2));
    float Ct = tanhf(p3);
    float c = F * g_Cst[idx] + I * Ct;
    g_Cst[idx] = c;
    float h = O * tanhf(c);
    const size_t hidx = (size_t)s * B_ * HID_ + idx;
    g_Hall[hidx] = h;
    g_PA[hidx] = __float2half(h);
}

// ---------------- persistent cooperative recurrence ----------------
__global__ __launch_bounds__(128, 1)
void lstm_persist(const float* __restrict__ Hin)
{
    extern __shared__ __align__(128) float sm[];
    float* hsm = sm;
    float* wsm = sm + 2 * 32 * 68;
    cg::grid_group grid = cg::this_grid();
    const int tid = threadIdx.x;
    const int blk = blockIdx.x;

    for (int s = 0; s < S_; ++s) {
        const float* hprev = (s == 0) ? Hin : (g_Hall + (size_t)(s - 1) * B_ * HID_);
        lstm_phaseA(hsm, wsm, hprev, blk, tid);
        grid.sync();
        lstm_phaseB_elem(s, blk * 256 + tid);
        lstm_phaseB_elem(s, blk * 256 + 128 + tid);
        grid.sync();
    }
}

// ---------------- fallback per-step kernels ----------------
__global__ __launch_bounds__(128)
void lstm_gemm_k(const float* __restrict__ Hin, int s)
{
    extern __shared__ __align__(128) float sm[];
    const float* hprev = (s == 0) ? Hin : (g_Hall + (size_t)(s - 1) * B_ * HID_);
    lstm_phaseA(sm, sm + 2 * 32 * 68, hprev, blockIdx.x, threadIdx.x);
}

__global__ void lstm_reduce_k(int s)
{
    int idx = blockIdx.x * 256 + threadIdx.x;
    lstm_phaseB_elem(s, idx);
}

// ---------------- tail: Hf, Cf ----------------
__global__ void tail_kernel(float* __restrict__ out, int out_size)
{
    const long YOFF = (long)SB_ * V_;
    int idx = blockIdx.x * blockDim.x + threadIdx.x;
    if ((long)out_size >= YOFF + 2L * B_ * HID_) {
        out[YOFF + idx] = g_Hall[(S_ - 1) * B_ * HID_ + idx];
        out[YOFF + B_ * HID_ + idx] = g_Cst[idx];
    }
}

// ---------------- launch ----------------
extern "C" void kernel_launch(void* const* d_in, const int* in_sizes, int n_in,
                              void* d_out, int out_size)
{
    const void*  X   = d_in[0];
    const float* H0  = (const float*)d_in[1];
    const float* C0  = (const float*)d_in[2];
    const float* emb = (const float*)d_in[3];
    const float* Wxi = (const float*)d_in[4];
    const float* Whi = (const float*)d_in[5];
    const float* bi  = (const float*)d_in[6];
    const float* Wxf = (const float*)d_in[7];
    const float* Whf = (const float*)d_in[8];
    const float* bf  = (const float*)d_in[9];
    const float* Wxo = (const float*)d_in[10];
    const float* Who = (const float*)d_in[11];
    const float* bo  = (const float*)d_in[12];
    const float* Wxc = (const float*)d_in[13];
    const float* Whc = (const float*)d_in[14];
    const float* bc  = (const float*)d_in[15];
    const float* Whq = (const float*)d_in[16];
    const float* bq  = (const float*)d_in[17];
    float* out = (float*)d_out;

    void *pXeHi, *pXeLo, *pWxTHi, *pWxTLo, *pPA, *pPB, *pb, *pXpre;
    cudaGetSymbolAddress(&pXeHi,  g_XeHi);
    cudaGetSymbolAddress(&pXeLo,  g_XeLo);
    cudaGetSymbolAddress(&pWxTHi, g_WxTHi);
    cudaGetSymbolAddress(&pWxTLo, g_WxTLo);
    cudaGetSymbolAddress(&pPA,    g_PA);
    cudaGetSymbolAddress(&pPB,    g_PB);
    cudaGetSymbolAddress(&pb,     g_bcat);
    cudaGetSymbolAddress(&pXpre,  g_Xpre);

    cudaFuncSetAttribute(gemm_mma,     cudaFuncAttributeMaxDynamicSharedMemorySize, GEMM_SMEM);
    cudaFuncSetAttribute(gemm_fp16,    cudaFuncAttributeMaxDynamicSharedMemorySize, GEMMH_SMEM);
    cudaFuncSetAttribute(lstm_persist, cudaFuncAttributeMaxDynamicSharedMemorySize, LSTM_SMEM);
    cudaFuncSetAttribute(lstm_gemm_k,  cudaFuncAttributeMaxDynamicSharedMemorySize, LSTM_SMEM);

    detect_kernel<<<1, 32>>>((const int*)X);
    prep_kernel<<<4096, 256>>>(Wxi, Whi, bi, Wxf, Whf, bf,
                               Wxo, Who, bo, Wxc, Whc, bc, C0);
    gather_kernel<<<4096, 256>>>(X, emb);
    wq_split<<<dim3(V_ / 32, HID_ / 32), dim3(32, 8)>>>(Whq);

    // Xpre = Xe @ Wx^T + bcat   (M=4096, N=4096, K=1024) — bf16 3-term (full precision)
    gemm_mma<<<dim3(SB_ / 128, G4_ / 128), 256, GEMM_SMEM>>>(
        (const __nv_bfloat16*)pXeHi, (const __nv_bfloat16*)pXeLo,
        (const __nv_bfloat16*)pWxTHi, (const __nv_bfloat16*)pWxTLo,
        (const float*)pb, (float*)pXpre, G4_);

    // recurrence: cooperative persistent kernel; fallback = per-step launches
    {
        const float* h0 = H0;
        void* args[1] = { (void*)&h0 };
        cudaError_t ce = cudaLaunchCooperativeKernel(
            (const void*)lstm_persist, dim3(128), dim3(128), args, (size_t)LSTM_SMEM, (cudaStream_t)0);
        if (ce != cudaSuccess) {
            cudaGetLastError();   // clear sticky error
            for (int s = 0; s < S_; ++s) {
                lstm_gemm_k<<<128, 128, LSTM_SMEM>>>(H0, s);
                lstm_reduce_k<<<128, 256>>>(s);
            }
        }
    }

    // Y = Hall @ Whq + bq  (M=4096, N=32000, K=1024) — single-pass fp16
    gemm_fp16<<<dim3(SB_ / 128, V_ / 128), 256, GEMMH_SMEM>>>(
        (const __half*)pPA, (const __half*)pPB, bq, out, V_);

    tail_kernel<<<128, 256>>>(out, out_size);
}